// round 6
// baseline (speedup 1.0000x reference)
#include <cuda_runtime.h>
#include <math.h>
#include <mma.h>

using namespace nvcuda;

// Problem constants (fixed by the dataset)
#define N_NODES 50000
#define N_PAD   50048                        // ceil(N/128)*128, for guard-free GEMM stores
#define E_EDGES 800000
#define E_TOT   (E_EDGES + N_NODES)
#define SCAN_NB ((N_NODES + 1023) / 1024)   // 49

// ---------------- scratch (static __device__ allocations only) ----------------
__device__ float g_h1 [(size_t)N_PAD * 128];   // x @ W1            [N,4,32]
__device__ float g_h1a[(size_t)N_PAD * 128];   // elu(gat1 output)  [N,128]
__device__ float g_h2 [(size_t)N_PAD * 256];   // h1a @ W2          [N,8,32]
__device__ float g_as1[N_NODES * 4];
__device__ float g_ad1[N_NODES * 4];
__device__ float g_as2[N_NODES * 8];
__device__ float g_ad2[N_NODES * 8];
__device__ int   g_cnt[N_NODES];
__device__ int   g_tmp[N_NODES];
__device__ int   g_bsum[SCAN_NB];
__device__ int   g_boff[SCAN_NB];
__device__ int   g_rowptr[N_NODES + 1];
__device__ int   g_cursor[N_NODES];
__device__ int   g_col[E_TOT];
__device__ int   g_is64;

// ---------------- dtype detection for edge_index (int64 vs int32) -------------
__global__ void detect64_kernel(const unsigned int* __restrict__ w) {
    __shared__ int any;
    if (threadIdx.x == 0) any = 0;
    __syncthreads();
    for (int i = 1 + 2 * threadIdx.x; i < 2048; i += 2 * blockDim.x)
        if (w[i] != 0u) any = 1;   // benign race
    __syncthreads();
    if (threadIdx.x == 0) g_is64 = (any == 0) ? 1 : 0;
}

__global__ void zero_cnt_kernel() {
    int i = blockIdx.x * blockDim.x + threadIdx.x;
    if (i < N_NODES) g_cnt[i] = 0;
}

__global__ void count_kernel(const void* __restrict__ ei) {
    int e = blockIdx.x * blockDim.x + threadIdx.x;
    if (e >= E_TOT) return;
    int dst;
    if (e < E_EDGES) {
        if (g_is64) dst = (int)((const long long*)ei)[(size_t)E_EDGES + e];
        else        dst = ((const int*)ei)[E_EDGES + e];
    } else {
        dst = e - E_EDGES;   // self loop
    }
    atomicAdd(&g_cnt[dst], 1);
}

// ---------------- multi-block scan (3 tiny kernels) ---------------------------
__global__ void scan1_kernel() {
    int b = blockIdx.x, tid = threadIdx.x;
    int i = b * 1024 + tid;
    int lane = tid & 31, wid = tid >> 5;
    int v = (i < N_NODES) ? g_cnt[i] : 0;
    int x = v;
#pragma unroll
    for (int off = 1; off < 32; off <<= 1) {
        int t = __shfl_up_sync(0xffffffffu, x, off);
        if (lane >= off) x += t;
    }
    __shared__ int wsum[32];
    if (lane == 31) wsum[wid] = x;
    __syncthreads();
    if (wid == 0) {
        int y = wsum[lane];
#pragma unroll
        for (int off = 1; off < 32; off <<= 1) {
            int t = __shfl_up_sync(0xffffffffu, y, off);
            if (lane >= off) y += t;
        }
        wsum[lane] = y;
    }
    __syncthreads();
    int incl = x + (wid ? wsum[wid - 1] : 0);
    if (i < N_NODES) g_tmp[i] = incl;
    if (tid == 1023) g_bsum[b] = incl;
}

__global__ void scan2_kernel() {
    if (threadIdx.x == 0) {
        int run = 0;
#pragma unroll 1
        for (int j = 0; j < SCAN_NB; j++) { g_boff[j] = run; run += g_bsum[j]; }
        g_rowptr[0] = 0;
    }
}

__global__ void scan3_kernel() {
    int i = blockIdx.x * blockDim.x + threadIdx.x;
    if (i >= N_NODES) return;
    int incl = g_tmp[i] + g_boff[i >> 10];
    g_rowptr[i + 1] = incl;
    g_cursor[i]     = incl - g_cnt[i];
}

__global__ void scatter_kernel(const void* __restrict__ ei) {
    int e = blockIdx.x * blockDim.x + threadIdx.x;
    if (e >= E_TOT) return;
    int src, dst;
    if (e < E_EDGES) {
        if (g_is64) {
            const long long* p = (const long long*)ei;
            src = (int)p[e];
            dst = (int)p[(size_t)E_EDGES + e];
        } else {
            const int* p = (const int*)ei;
            src = p[e];
            dst = p[E_EDGES + e];
        }
    } else {
        src = dst = e - E_EDGES;
    }
    int pos = atomicAdd(&g_cursor[dst], 1);
    g_col[pos] = src;
}

// ---------------- 3xTF32 tensor-core GEMM -------------------------------------
// C[M_pad, N] = A[M, K] @ B[K, N]  (A loads guarded by M, stores unguarded into
// padded C). Block tile 128x64, 8 warps (4x2), warp tile 32x32, BK=32.
#define GM_BM 128
#define GM_BN 64
#define GM_BK 32
#define GLDA 40   // padded leading dims (floats); keep rows 32B-aligned
#define GLDB 72

__global__ void tf32_gemm_kernel(const float* __restrict__ A,
                                 const float* __restrict__ B,
                                 float* __restrict__ C,
                                 int M, int N, int K) {
    __shared__ float As[GM_BM * GLDA];
    __shared__ float Bs[GM_BK * GLDB];
    int tid = threadIdx.x;
    int wid = tid >> 5;
    int wm = wid & 3;       // 0..3 : M direction
    int wn = wid >> 2;      // 0..1 : N direction
    int row0 = blockIdx.y * GM_BM;
    int col0 = blockIdx.x * GM_BN;

    wmma::fragment<wmma::accumulator, 16, 16, 8, float> c[2][2];
#pragma unroll
    for (int i = 0; i < 2; i++)
#pragma unroll
        for (int j = 0; j < 2; j++) wmma::fill_fragment(c[i][j], 0.f);

    for (int k0 = 0; k0 < K; k0 += GM_BK) {
        // A tile: 128x32 floats = 1024 float4, 4 per thread
#pragma unroll
        for (int i = 0; i < 4; i++) {
            int f = tid + i * 256;
            int r = f >> 3, cc = (f & 7) * 4;
            float4 v = make_float4(0.f, 0.f, 0.f, 0.f);
            if (row0 + r < M)
                v = *(const float4*)(A + (size_t)(row0 + r) * K + k0 + cc);
            *(float4*)(As + r * GLDA + cc) = v;
        }
        // B tile: 32x64 floats = 512 float4, 2 per thread
#pragma unroll
        for (int i = 0; i < 2; i++) {
            int f = tid + i * 256;
            int r = f >> 4, cc = (f & 15) * 4;
            float4 v = *(const float4*)(B + (size_t)(k0 + r) * N + col0 + cc);
            *(float4*)(Bs + r * GLDB + cc) = v;
        }
        __syncthreads();
#pragma unroll
        for (int kk = 0; kk < GM_BK; kk += 8) {
            wmma::fragment<wmma::matrix_a, 16, 16, 8, wmma::precision::tf32, wmma::row_major> ahi[2], alo[2];
            wmma::fragment<wmma::matrix_b, 16, 16, 8, wmma::precision::tf32, wmma::row_major> bhi[2], blo[2];
#pragma unroll
            for (int mi = 0; mi < 2; mi++) {
                wmma::load_matrix_sync(ahi[mi], As + (wm * 32 + mi * 16) * GLDA + kk, GLDA);
#pragma unroll
                for (int t = 0; t < ahi[mi].num_elements; t++) {
                    float x = ahi[mi].x[t];
                    float h = wmma::__float_to_tf32(x);
                    ahi[mi].x[t] = h;
                    alo[mi].x[t] = wmma::__float_to_tf32(x - h);
                }
            }
#pragma unroll
            for (int ni = 0; ni < 2; ni++) {
                wmma::load_matrix_sync(bhi[ni], Bs + kk * GLDB + wn * 32 + ni * 16, GLDB);
#pragma unroll
                for (int t = 0; t < bhi[ni].num_elements; t++) {
                    float x = bhi[ni].x[t];
                    float h = wmma::__float_to_tf32(x);
                    bhi[ni].x[t] = h;
                    blo[ni].x[t] = wmma::__float_to_tf32(x - h);
                }
            }
#pragma unroll
            for (int mi = 0; mi < 2; mi++)
#pragma unroll
                for (int ni = 0; ni < 2; ni++) {
                    wmma::mma_sync(c[mi][ni], alo[mi], bhi[ni], c[mi][ni]);
                    wmma::mma_sync(c[mi][ni], ahi[mi], blo[ni], c[mi][ni]);
                    wmma::mma_sync(c[mi][ni], ahi[mi], bhi[ni], c[mi][ni]);
                }
        }
        __syncthreads();
    }
#pragma unroll
    for (int mi = 0; mi < 2; mi++)
#pragma unroll
        for (int ni = 0; ni < 2; ni++)
            wmma::store_matrix_sync(
                C + (size_t)(row0 + wm * 32 + mi * 16) * N + col0 + wn * 32 + ni * 16,
                c[mi][ni], N, wmma::mem_row_major);
}

// ---------------- per-node attention coefficients -----------------------------
template <int H>
__global__ void alpha_kernel(const float* __restrict__ h,
                             const float* __restrict__ att_s,
                             const float* __restrict__ att_d,
                             float* __restrict__ as_out,
                             float* __restrict__ ad_out) {
    int idx = blockIdx.x * blockDim.x + threadIdx.x;
    if (idx >= N_NODES * H) return;
    int node = idx / H, hh = idx % H;
    const float* hp = h + (size_t)node * H * 32 + hh * 32;
    const float* a1 = att_s + hh * 32;
    const float* a2 = att_d + hh * 32;
    float s1 = 0.f, s2 = 0.f;
#pragma unroll
    for (int c = 0; c < 32; c += 4) {
        float4 v  = *(const float4*)(hp + c);
        float4 w1 = *(const float4*)(a1 + c);
        float4 w2 = *(const float4*)(a2 + c);
        s1 += v.x * w1.x + v.y * w1.y + v.z * w1.z + v.w * w1.w;
        s2 += v.x * w2.x + v.y * w2.y + v.z * w2.z + v.w * w2.w;
    }
    as_out[idx] = s1;
    ad_out[idx] = s2;
}

// ---------------- fused single-pass GAT edge aggregation ----------------------
// One warp per destination node; lanes = channels (32), heads in registers.
// Exact online softmax with accumulator rescale: when the running max rises,
// acc and s are rescaled by exp(m_old - m_new). Single walk over the edges.
template <int H, bool ELU_OUT, bool MEAN_OUT>
__global__ void gat_edge_fused_kernel(const float* __restrict__ hfeat,
                                      const float* __restrict__ asrc,
                                      const float* __restrict__ adst,
                                      const float* __restrict__ bias,
                                      float* __restrict__ out) {
    int w    = (blockIdx.x * blockDim.x + threadIdx.x) >> 5;
    int lane = threadIdx.x & 31;
    if (w >= N_NODES) return;
    int beg = g_rowptr[w], end = g_rowptr[w + 1];

    float ad[H];
#pragma unroll
    for (int h = 0; h < H; h++) ad[h] = adst[(size_t)w * H + h];

    float m[H], s[H], acc[H];
#pragma unroll
    for (int h = 0; h < H; h++) { m[h] = -1e30f; s[h] = 0.f; acc[h] = 0.f; }

    for (int e = beg; e < end; e++) {
        int src = g_col[e];
        const float4* ap4 = (const float4*)(asrc + (size_t)src * H);   // broadcast
        const float*  hp  = hfeat + (size_t)src * (H * 32);
        float av[H];
#pragma unroll
        for (int q = 0; q < H / 4; q++) {
            float4 t = ap4[q];
            av[4 * q] = t.x; av[4 * q + 1] = t.y; av[4 * q + 2] = t.z; av[4 * q + 3] = t.w;
        }
#pragma unroll
        for (int h = 0; h < H; h++) {
            float x = av[h] + ad[h];
            x = x > 0.f ? x : 0.2f * x;
            float hv = hp[h * 32 + lane];
            if (x > m[h]) {                      // warp-uniform branch
                float r = __expf(m[h] - x);      // first edge: exp(-huge)=0
                s[h]   = s[h]   * r + 1.f;
                acc[h] = acc[h] * r + hv;
                m[h]   = x;
            } else {
                float wt = __expf(x - m[h]);
                s[h]   += wt;
                acc[h] += hv * wt;
            }
        }
    }

    if (MEAN_OUT) {
        float v = 0.f;
#pragma unroll
        for (int h = 0; h < H; h++) v += acc[h] / s[h];
        out[(size_t)w * 32 + lane] = v * (1.f / H) + bias[lane];
    } else {
#pragma unroll
        for (int h = 0; h < H; h++) {
            float v = acc[h] / s[h] + bias[h * 32 + lane];
            if (ELU_OUT) v = v > 0.f ? v : expm1f(v);
            out[(size_t)w * (H * 32) + h * 32 + lane] = v;
        }
    }
}

// ---------------- launch ------------------------------------------------------
extern "C" void kernel_launch(void* const* d_in, const int* in_sizes, int n_in,
                              void* d_out, int out_size) {
    const float* x   = (const float*)d_in[0];
    const void*  ei  = d_in[1];
    const float* W1  = (const float*)d_in[2];
    const float* at_s1 = (const float*)d_in[3];
    const float* at_d1 = (const float*)d_in[4];
    const float* b1  = (const float*)d_in[5];
    const float* W2  = (const float*)d_in[6];
    const float* at_s2 = (const float*)d_in[7];
    const float* at_d2 = (const float*)d_in[8];
    const float* b2  = (const float*)d_in[9];
    float* out = (float*)d_out;

    float *h1, *h1a, *h2, *pas1, *pad1, *pas2, *pad2;
    cudaGetSymbolAddress((void**)&h1,  g_h1);
    cudaGetSymbolAddress((void**)&h1a, g_h1a);
    cudaGetSymbolAddress((void**)&h2,  g_h2);
    cudaGetSymbolAddress((void**)&pas1, g_as1);
    cudaGetSymbolAddress((void**)&pad1, g_ad1);
    cudaGetSymbolAddress((void**)&pas2, g_as2);
    cudaGetSymbolAddress((void**)&pad2, g_ad2);

    // CSR build (sorted-by-destination adjacency, self loops appended)
    detect64_kernel<<<1, 256>>>((const unsigned int*)ei);
    zero_cnt_kernel<<<(N_NODES + 255) / 256, 256>>>();
    count_kernel<<<(E_TOT + 255) / 256, 256>>>(ei);
    scan1_kernel<<<SCAN_NB, 1024>>>();
    scan2_kernel<<<1, 32>>>();
    scan3_kernel<<<(N_NODES + 255) / 256, 256>>>();
    scatter_kernel<<<(E_TOT + 255) / 256, 256>>>(ei);

    dim3 gemm_grid1(128 / GM_BN, (N_NODES + GM_BM - 1) / GM_BM);
    dim3 gemm_grid2(256 / GM_BN, (N_NODES + GM_BM - 1) / GM_BM);

    // layer 1
    tf32_gemm_kernel<<<gemm_grid1, 256>>>(x, W1, h1, N_NODES, 128, 128);
    alpha_kernel<4><<<(N_NODES * 4 + 255) / 256, 256>>>(h1, at_s1, at_d1, pas1, pad1);
    gat_edge_fused_kernel<4, true, false><<<(N_NODES + 7) / 8, 256>>>(h1, pas1, pad1, b1, h1a);

    // layer 2
    tf32_gemm_kernel<<<gemm_grid2, 256>>>(h1a, W2, h2, N_NODES, 256, 128);
    alpha_kernel<8><<<(N_NODES * 8 + 255) / 256, 256>>>(h2, at_s2, at_d2, pas2, pad2);
    gat_edge_fused_kernel<8, false, true><<<(N_NODES + 7) / 8, 256>>>(h2, pas2, pad2, b2, out);
}

// round 7
// speedup vs baseline: 1.0588x; 1.0588x over previous
#include <cuda_runtime.h>
#include <math.h>

// Problem constants (fixed by the dataset)
#define N_NODES 50000
#define N_PAD   50048                        // ceil(N/128)*128, for guard-free GEMM stores
#define E_EDGES 800000
#define E_TOT   (E_EDGES + N_NODES)
#define SCAN_NB ((N_NODES + 1023) / 1024)   // 49

// ---------------- scratch (static __device__ allocations only) ----------------
__device__ float g_h1 [(size_t)N_PAD * 128];   // x @ W1            [N,4,32]
__device__ float g_h1a[(size_t)N_PAD * 128];   // elu(gat1 output)  [N,128]
__device__ float g_h2 [(size_t)N_PAD * 256];   // h1a @ W2          [N,8,32]
__device__ float g_as1[N_NODES * 4];
__device__ float g_ad1[N_NODES * 4];
__device__ float g_as2[N_NODES * 8];
__device__ float g_ad2[N_NODES * 8];
__device__ int   g_cnt[N_NODES];
__device__ int   g_tmp[N_NODES];
__device__ int   g_bsum[SCAN_NB];
__device__ int   g_boff[SCAN_NB];
__device__ int   g_rowptr[N_NODES + 1];
__device__ int   g_cursor[N_NODES];
__device__ int   g_col[E_TOT];
__device__ int   g_is64;

// ---------------- dtype detection for edge_index (int64 vs int32) -------------
__global__ void detect64_kernel(const unsigned int* __restrict__ w) {
    __shared__ int any;
    if (threadIdx.x == 0) any = 0;
    __syncthreads();
    for (int i = 1 + 2 * threadIdx.x; i < 2048; i += 2 * blockDim.x)
        if (w[i] != 0u) any = 1;   // benign race
    __syncthreads();
    if (threadIdx.x == 0) g_is64 = (any == 0) ? 1 : 0;
}

__global__ void zero_cnt_kernel() {
    int i = blockIdx.x * blockDim.x + threadIdx.x;
    if (i < N_NODES) g_cnt[i] = 0;
}

__global__ void count_kernel(const void* __restrict__ ei) {
    int e = blockIdx.x * blockDim.x + threadIdx.x;
    if (e >= E_TOT) return;
    int dst;
    if (e < E_EDGES) {
        if (g_is64) dst = (int)((const long long*)ei)[(size_t)E_EDGES + e];
        else        dst = ((const int*)ei)[E_EDGES + e];
    } else {
        dst = e - E_EDGES;   // self loop
    }
    atomicAdd(&g_cnt[dst], 1);
}

// ---------------- multi-block scan (3 tiny kernels) ---------------------------
__global__ void scan1_kernel() {
    int b = blockIdx.x, tid = threadIdx.x;
    int i = b * 1024 + tid;
    int lane = tid & 31, wid = tid >> 5;
    int v = (i < N_NODES) ? g_cnt[i] : 0;
    int x = v;
#pragma unroll
    for (int off = 1; off < 32; off <<= 1) {
        int t = __shfl_up_sync(0xffffffffu, x, off);
        if (lane >= off) x += t;
    }
    __shared__ int wsum[32];
    if (lane == 31) wsum[wid] = x;
    __syncthreads();
    if (wid == 0) {
        int y = wsum[lane];
#pragma unroll
        for (int off = 1; off < 32; off <<= 1) {
            int t = __shfl_up_sync(0xffffffffu, y, off);
            if (lane >= off) y += t;
        }
        wsum[lane] = y;
    }
    __syncthreads();
    int incl = x + (wid ? wsum[wid - 1] : 0);
    if (i < N_NODES) g_tmp[i] = incl;
    if (tid == 1023) g_bsum[b] = incl;
}

__global__ void scan2_kernel() {
    if (threadIdx.x == 0) {
        int run = 0;
#pragma unroll 1
        for (int j = 0; j < SCAN_NB; j++) { g_boff[j] = run; run += g_bsum[j]; }
        g_rowptr[0] = 0;
    }
}

__global__ void scan3_kernel() {
    int i = blockIdx.x * blockDim.x + threadIdx.x;
    if (i >= N_NODES) return;
    int incl = g_tmp[i] + g_boff[i >> 10];
    g_rowptr[i + 1] = incl;
    g_cursor[i]     = incl - g_cnt[i];
}

__global__ void scatter_kernel(const void* __restrict__ ei) {
    int e = blockIdx.x * blockDim.x + threadIdx.x;
    if (e >= E_TOT) return;
    int src, dst;
    if (e < E_EDGES) {
        if (g_is64) {
            const long long* p = (const long long*)ei;
            src = (int)p[e];
            dst = (int)p[(size_t)E_EDGES + e];
        } else {
            const int* p = (const int*)ei;
            src = p[e];
            dst = p[E_EDGES + e];
        }
    } else {
        src = dst = e - E_EDGES;
    }
    int pos = atomicAdd(&g_cursor[dst], 1);
    g_col[pos] = src;
}

// ---------------- SIMT SGEMM: C[M_pad, N] = A[M, K] @ B[K, N] -----------------
// 128x128 block tile, 256 threads (16x16), 8x8 per-thread register tile, BK=8.
// A loads guarded by M; stores unguarded into padded C.
#define SG_BM 128
#define SG_BN 128
#define SG_BK 8

__global__ void sgemm128_kernel(const float* __restrict__ A,
                                const float* __restrict__ B,
                                float* __restrict__ C,
                                int M, int N, int K) {
    __shared__ float As[SG_BK][SG_BM];
    __shared__ float Bs[SG_BK][SG_BN];
    int tid = threadIdx.x;
    int tx = tid & 15, ty = tid >> 4;
    int row0 = blockIdx.y * SG_BM;
    int col0 = blockIdx.x * SG_BN;

    float acc[8][8];
#pragma unroll
    for (int i = 0; i < 8; i++)
#pragma unroll
        for (int j = 0; j < 8; j++) acc[i][j] = 0.f;

    int a_r = tid >> 1, a_c = (tid & 1) * 4;   // A tile: 128x8, 1 float4/thread
    int b_r = tid >> 5, b_c = (tid & 31) * 4;  // B tile: 8x128,  1 float4/thread

    for (int k0 = 0; k0 < K; k0 += SG_BK) {
        float4 av = make_float4(0.f, 0.f, 0.f, 0.f);
        if (row0 + a_r < M)
            av = *(const float4*)(A + (size_t)(row0 + a_r) * K + k0 + a_c);
        As[a_c + 0][a_r] = av.x;
        As[a_c + 1][a_r] = av.y;
        As[a_c + 2][a_r] = av.z;
        As[a_c + 3][a_r] = av.w;
        float4 bv = *(const float4*)(B + (size_t)(k0 + b_r) * N + col0 + b_c);
        *(float4*)&Bs[b_r][b_c] = bv;
        __syncthreads();
#pragma unroll
        for (int kk = 0; kk < SG_BK; kk++) {
            float ar[8], br[8];
            *(float4*)&ar[0] = *(float4*)&As[kk][ty * 8];
            *(float4*)&ar[4] = *(float4*)&As[kk][ty * 8 + 4];
            *(float4*)&br[0] = *(float4*)&Bs[kk][tx * 8];
            *(float4*)&br[4] = *(float4*)&Bs[kk][tx * 8 + 4];
#pragma unroll
            for (int i = 0; i < 8; i++)
#pragma unroll
                for (int j = 0; j < 8; j++)
                    acc[i][j] += ar[i] * br[j];
        }
        __syncthreads();
    }
#pragma unroll
    for (int i = 0; i < 8; i++) {
        float* cp = C + (size_t)(row0 + ty * 8 + i) * N + col0 + tx * 8;
        *(float4*)cp       = *(float4*)&acc[i][0];
        *(float4*)(cp + 4) = *(float4*)&acc[i][4];
    }
}

// ---------------- per-node attention coefficients -----------------------------
template <int H>
__global__ void alpha_kernel(const float* __restrict__ h,
                             const float* __restrict__ att_s,
                             const float* __restrict__ att_d,
                             float* __restrict__ as_out,
                             float* __restrict__ ad_out) {
    int idx = blockIdx.x * blockDim.x + threadIdx.x;
    if (idx >= N_NODES * H) return;
    int node = idx / H, hh = idx % H;
    const float* hp = h + (size_t)node * H * 32 + hh * 32;
    const float* a1 = att_s + hh * 32;
    const float* a2 = att_d + hh * 32;
    float s1 = 0.f, s2 = 0.f;
#pragma unroll
    for (int c = 0; c < 32; c += 4) {
        float4 v  = *(const float4*)(hp + c);
        float4 w1 = *(const float4*)(a1 + c);
        float4 w2 = *(const float4*)(a2 + c);
        s1 += v.x * w1.x + v.y * w1.y + v.z * w1.z + v.w * w1.w;
        s2 += v.x * w2.x + v.y * w2.y + v.z * w2.z + v.w * w2.w;
    }
    as_out[idx] = s1;
    ad_out[idx] = s2;
}

// ---------------- fused single-pass GAT edge aggregation ----------------------
// One warp per destination node; lanes = channels (32), heads in registers.
// Exact online softmax with accumulator rescale (warp-uniform branch).
template <int H, bool ELU_OUT, bool MEAN_OUT>
__global__ void gat_edge_fused_kernel(const float* __restrict__ hfeat,
                                      const float* __restrict__ asrc,
                                      const float* __restrict__ adst,
                                      const float* __restrict__ bias,
                                      float* __restrict__ out) {
    int w    = (blockIdx.x * blockDim.x + threadIdx.x) >> 5;
    int lane = threadIdx.x & 31;
    if (w >= N_NODES) return;
    int beg = g_rowptr[w], end = g_rowptr[w + 1];

    float ad[H];
#pragma unroll
    for (int h = 0; h < H; h++) ad[h] = adst[(size_t)w * H + h];

    float m[H], s[H], acc[H];
#pragma unroll
    for (int h = 0; h < H; h++) { m[h] = -1e30f; s[h] = 0.f; acc[h] = 0.f; }

    for (int e = beg; e < end; e++) {
        int src = g_col[e];
        const float4* ap4 = (const float4*)(asrc + (size_t)src * H);   // broadcast
        const float*  hp  = hfeat + (size_t)src * (H * 32);
        float av[H];
#pragma unroll
        for (int q = 0; q < H / 4; q++) {
            float4 t = ap4[q];
            av[4 * q] = t.x; av[4 * q + 1] = t.y; av[4 * q + 2] = t.z; av[4 * q + 3] = t.w;
        }
#pragma unroll
        for (int h = 0; h < H; h++) {
            float x = av[h] + ad[h];
            x = x > 0.f ? x : 0.2f * x;
            float hv = hp[h * 32 + lane];
            if (x > m[h]) {                      // warp-uniform branch
                float r = __expf(m[h] - x);      // first edge: exp(-huge)=0
                s[h]   = s[h]   * r + 1.f;
                acc[h] = acc[h] * r + hv;
                m[h]   = x;
            } else {
                float wt = __expf(x - m[h]);
                s[h]   += wt;
                acc[h] += hv * wt;
            }
        }
    }

    if (MEAN_OUT) {
        float v = 0.f;
#pragma unroll
        for (int h = 0; h < H; h++) v += acc[h] / s[h];
        out[(size_t)w * 32 + lane] = v * (1.f / H) + bias[lane];
    } else {
#pragma unroll
        for (int h = 0; h < H; h++) {
            float v = acc[h] / s[h] + bias[h * 32 + lane];
            if (ELU_OUT) v = v > 0.f ? v : expm1f(v);
            out[(size_t)w * (H * 32) + h * 32 + lane] = v;
        }
    }
}

// ---------------- launch ------------------------------------------------------
extern "C" void kernel_launch(void* const* d_in, const int* in_sizes, int n_in,
                              void* d_out, int out_size) {
    const float* x   = (const float*)d_in[0];
    const void*  ei  = d_in[1];
    const float* W1  = (const float*)d_in[2];
    const float* at_s1 = (const float*)d_in[3];
    const float* at_d1 = (const float*)d_in[4];
    const float* b1  = (const float*)d_in[5];
    const float* W2  = (const float*)d_in[6];
    const float* at_s2 = (const float*)d_in[7];
    const float* at_d2 = (const float*)d_in[8];
    const float* b2  = (const float*)d_in[9];
    float* out = (float*)d_out;

    float *h1, *h1a, *h2, *pas1, *pad1, *pas2, *pad2;
    cudaGetSymbolAddress((void**)&h1,  g_h1);
    cudaGetSymbolAddress((void**)&h1a, g_h1a);
    cudaGetSymbolAddress((void**)&h2,  g_h2);
    cudaGetSymbolAddress((void**)&pas1, g_as1);
    cudaGetSymbolAddress((void**)&pad1, g_ad1);
    cudaGetSymbolAddress((void**)&pas2, g_as2);
    cudaGetSymbolAddress((void**)&pad2, g_ad2);

    // CSR build (sorted-by-destination adjacency, self loops appended)
    detect64_kernel<<<1, 256>>>((const unsigned int*)ei);
    zero_cnt_kernel<<<(N_NODES + 255) / 256, 256>>>();
    count_kernel<<<(E_TOT + 255) / 256, 256>>>(ei);
    scan1_kernel<<<SCAN_NB, 1024>>>();
    scan2_kernel<<<1, 32>>>();
    scan3_kernel<<<(N_NODES + 255) / 256, 256>>>();
    scatter_kernel<<<(E_TOT + 255) / 256, 256>>>(ei);

    dim3 gemm_grid1(128 / SG_BN, (N_NODES + SG_BM - 1) / SG_BM);   // (1, 391)
    dim3 gemm_grid2(256 / SG_BN, (N_NODES + SG_BM - 1) / SG_BM);   // (2, 391)

    // layer 1
    sgemm128_kernel<<<gemm_grid1, 256>>>(x, W1, h1, N_NODES, 128, 128);
    alpha_kernel<4><<<(N_NODES * 4 + 255) / 256, 256>>>(h1, at_s1, at_d1, pas1, pad1);
    gat_edge_fused_kernel<4, true, false><<<(N_NODES + 7) / 8, 256>>>(h1, pas1, pad1, b1, h1a);

    // layer 2
    sgemm128_kernel<<<gemm_grid2, 256>>>(h1a, W2, h2, N_NODES, 256, 128);
    alpha_kernel<8><<<(N_NODES * 8 + 255) / 256, 256>>>(h2, at_s2, at_d2, pas2, pad2);
    gat_edge_fused_kernel<8, false, true><<<(N_NODES + 7) / 8, 256>>>(h2, pas2, pad2, b2, out);
}

// round 9
// speedup vs baseline: 1.3157x; 1.2426x over previous
#include <cuda_runtime.h>
#include <math.h>

// Problem constants (fixed by the dataset)
#define N_NODES 50000
#define N_PAD   50048                        // ceil(N/128)*128, for guard-free GEMM stores
#define E_EDGES 800000
#define E_TOT   (E_EDGES + N_NODES)
#define SCAN_NB ((N_NODES + 1023) / 1024)   // 49

// ---------------- scratch (static __device__ allocations only) ----------------
__device__ float g_h1 [(size_t)N_PAD * 128];   // x @ W1            [N,4,32]
__device__ float g_h1a[(size_t)N_PAD * 128];   // elu(gat1 output)  [N,128]
__device__ float g_h2 [(size_t)N_PAD * 256];   // h1a @ W2          [N,8,32]
__device__ float g_as1[N_NODES * 4];
__device__ float g_ad1[N_NODES * 4];
__device__ float g_as2[N_NODES * 8];
__device__ float g_ad2[N_NODES * 8];
__device__ int   g_cnt[N_NODES];
__device__ int   g_tmp[N_NODES];
__device__ int   g_bsum[SCAN_NB];
__device__ int   g_boff[SCAN_NB];
__device__ int   g_rowptr[N_NODES + 1];
__device__ int   g_cursor[N_NODES];
__device__ int   g_col[E_TOT];
__device__ int   g_is64;

// ---------------- dtype detection for edge_index (int64 vs int32) -------------
__global__ void detect64_kernel(const unsigned int* __restrict__ w) {
    __shared__ int any;
    if (threadIdx.x == 0) any = 0;
    __syncthreads();
    for (int i = 1 + 2 * threadIdx.x; i < 2048; i += 2 * blockDim.x)
        if (w[i] != 0u) any = 1;   // benign race
    __syncthreads();
    if (threadIdx.x == 0) g_is64 = (any == 0) ? 1 : 0;
}

__global__ void zero_cnt_kernel() {
    int i = blockIdx.x * blockDim.x + threadIdx.x;
    if (i < N_NODES) g_cnt[i] = 0;
}

__global__ void count_kernel(const void* __restrict__ ei) {
    int e = blockIdx.x * blockDim.x + threadIdx.x;
    if (e >= E_TOT) return;
    int dst;
    if (e < E_EDGES) {
        if (g_is64) dst = (int)((const long long*)ei)[(size_t)E_EDGES + e];
        else        dst = ((const int*)ei)[E_EDGES + e];
    } else {
        dst = e - E_EDGES;   // self loop
    }
    atomicAdd(&g_cnt[dst], 1);
}

// ---------------- multi-block scan (3 tiny kernels) ---------------------------
__global__ void scan1_kernel() {
    int b = blockIdx.x, tid = threadIdx.x;
    int i = b * 1024 + tid;
    int lane = tid & 31, wid = tid >> 5;
    int v = (i < N_NODES) ? g_cnt[i] : 0;
    int x = v;
#pragma unroll
    for (int off = 1; off < 32; off <<= 1) {
        int t = __shfl_up_sync(0xffffffffu, x, off);
        if (lane >= off) x += t;
    }
    __shared__ int wsum[32];
    if (lane == 31) wsum[wid] = x;
    __syncthreads();
    if (wid == 0) {
        int y = wsum[lane];
#pragma unroll
        for (int off = 1; off < 32; off <<= 1) {
            int t = __shfl_up_sync(0xffffffffu, y, off);
            if (lane >= off) y += t;
        }
        wsum[lane] = y;
    }
    __syncthreads();
    int incl = x + (wid ? wsum[wid - 1] : 0);
    if (i < N_NODES) g_tmp[i] = incl;
    if (tid == 1023) g_bsum[b] = incl;
}

__global__ void scan2_kernel() {
    if (threadIdx.x == 0) {
        int run = 0;
#pragma unroll 1
        for (int j = 0; j < SCAN_NB; j++) { g_boff[j] = run; run += g_bsum[j]; }
        g_rowptr[0] = 0;
    }
}

__global__ void scan3_kernel() {
    int i = blockIdx.x * blockDim.x + threadIdx.x;
    if (i >= N_NODES) return;
    int incl = g_tmp[i] + g_boff[i >> 10];
    g_rowptr[i + 1] = incl;
    g_cursor[i]     = incl - g_cnt[i];
}

__global__ void scatter_kernel(const void* __restrict__ ei) {
    int e = blockIdx.x * blockDim.x + threadIdx.x;
    if (e >= E_TOT) return;
    int src, dst;
    if (e < E_EDGES) {
        if (g_is64) {
            const long long* p = (const long long*)ei;
            src = (int)p[e];
            dst = (int)p[(size_t)E_EDGES + e];
        } else {
            const int* p = (const int*)ei;
            src = p[e];
            dst = p[E_EDGES + e];
        }
    } else {
        src = dst = e - E_EDGES;
    }
    int pos = atomicAdd(&g_cursor[dst], 1);
    g_col[pos] = src;
}

// ------------- double-buffered SIMT SGEMM: C[M_pad,N] = A[M,K] @ B[K,N] -------
// 128x128 block tile, 256 threads (16x16), 8x8 register tile, BK=8,
// 2-stage smem pipeline: global->regs prefetch overlaps FFMA on current tile.
#define SG_BM 128
#define SG_BN 128
#define SG_BK 8

__global__ void sgemm128db_kernel(const float* __restrict__ A,
                                  const float* __restrict__ B,
                                  float* __restrict__ C,
                                  int M, int N, int K) {
    __shared__ float As[2][SG_BK][SG_BM];
    __shared__ float Bs[2][SG_BK][SG_BN];
    int tid = threadIdx.x;
    int tx = tid & 15, ty = tid >> 4;
    int row0 = blockIdx.y * SG_BM;
    int col0 = blockIdx.x * SG_BN;

    int a_r = tid >> 1, a_c = (tid & 1) * 4;   // A tile: 128x8, 1 float4/thread
    int b_r = tid >> 5, b_c = (tid & 31) * 4;  // B tile: 8x128,  1 float4/thread

    float acc[8][8];
#pragma unroll
    for (int i = 0; i < 8; i++)
#pragma unroll
        for (int j = 0; j < 8; j++) acc[i][j] = 0.f;

    // preload tile 0 into buffer 0
    {
        float4 av = make_float4(0.f, 0.f, 0.f, 0.f);
        if (row0 + a_r < M)
            av = *(const float4*)(A + (size_t)(row0 + a_r) * K + a_c);
        As[0][a_c + 0][a_r] = av.x;
        As[0][a_c + 1][a_r] = av.y;
        As[0][a_c + 2][a_r] = av.z;
        As[0][a_c + 3][a_r] = av.w;
        float4 bv = *(const float4*)(B + (size_t)b_r * N + col0 + b_c);
        *(float4*)&Bs[0][b_r][b_c] = bv;
    }
    __syncthreads();

    int nk = K / SG_BK;
    for (int t = 0; t < nk; t++) {
        int cur = t & 1;
        float4 av, bv;
        bool more = (t + 1 < nk);
        if (more) {   // prefetch next tile into registers
            int k0 = (t + 1) * SG_BK;
            av = make_float4(0.f, 0.f, 0.f, 0.f);
            if (row0 + a_r < M)
                av = *(const float4*)(A + (size_t)(row0 + a_r) * K + k0 + a_c);
            bv = *(const float4*)(B + (size_t)(k0 + b_r) * N + col0 + b_c);
        }
#pragma unroll
        for (int kk = 0; kk < SG_BK; kk++) {
            float ar[8], br[8];
            *(float4*)&ar[0] = *(float4*)&As[cur][kk][ty * 8];
            *(float4*)&ar[4] = *(float4*)&As[cur][kk][ty * 8 + 4];
            *(float4*)&br[0] = *(float4*)&Bs[cur][kk][tx * 8];
            *(float4*)&br[4] = *(float4*)&Bs[cur][kk][tx * 8 + 4];
#pragma unroll
            for (int i = 0; i < 8; i++)
#pragma unroll
                for (int j = 0; j < 8; j++)
                    acc[i][j] += ar[i] * br[j];
        }
        if (more) {
            int nxt = cur ^ 1;
            As[nxt][a_c + 0][a_r] = av.x;
            As[nxt][a_c + 1][a_r] = av.y;
            As[nxt][a_c + 2][a_r] = av.z;
            As[nxt][a_c + 3][a_r] = av.w;
            *(float4*)&Bs[nxt][b_r][b_c] = bv;
            __syncthreads();
        }
    }
#pragma unroll
    for (int i = 0; i < 8; i++) {
        float* cp = C + (size_t)(row0 + ty * 8 + i) * N + col0 + tx * 8;
        *(float4*)cp       = *(float4*)&acc[i][0];
        *(float4*)(cp + 4) = *(float4*)&acc[i][4];
    }
}

// ---------------- per-node attention coefficients -----------------------------
template <int H>
__global__ void alpha_kernel(const float* __restrict__ h,
                             const float* __restrict__ att_s,
                             const float* __restrict__ att_d,
                             float* __restrict__ as_out,
                             float* __restrict__ ad_out) {
    int idx = blockIdx.x * blockDim.x + threadIdx.x;
    if (idx >= N_NODES * H) return;
    int node = idx / H, hh = idx % H;
    const float* hp = h + (size_t)node * H * 32 + hh * 32;
    const float* a1 = att_s + hh * 32;
    const float* a2 = att_d + hh * 32;
    float s1 = 0.f, s2 = 0.f;
#pragma unroll
    for (int c = 0; c < 32; c += 4) {
        float4 v  = *(const float4*)(hp + c);
        float4 w1 = *(const float4*)(a1 + c);
        float4 w2 = *(const float4*)(a2 + c);
        s1 += v.x * w1.x + v.y * w1.y + v.z * w1.z + v.w * w1.w;
        s2 += v.x * w2.x + v.y * w2.y + v.z * w2.z + v.w * w2.w;
    }
    as_out[idx] = s1;
    ad_out[idx] = s2;
}

// ---------------- GAT edge aggregation: one warp per destination node ---------
// R4-measured-good two-pass form. Pass A: ONLINE softmax, lane-parallel.
// Pass B: branchless weighted accumulation, serial edges / lane channels.
template <int H, bool ELU_OUT, bool MEAN_OUT>
__global__ void gat_edge_kernel(const float* __restrict__ hfeat,
                                const float* __restrict__ asrc,
                                const float* __restrict__ adst,
                                const float* __restrict__ bias,
                                float* __restrict__ out) {
    int w    = (blockIdx.x * blockDim.x + threadIdx.x) >> 5;
    int lane = threadIdx.x & 31;
    if (w >= N_NODES) return;
    int beg = g_rowptr[w], end = g_rowptr[w + 1];

    float ad[H];
#pragma unroll
    for (int h = 0; h < H; h++) ad[h] = adst[(size_t)w * H + h];

    // pass A: online max + sum over edges (lane-parallel)
    float m[H], s[H];
#pragma unroll
    for (int h = 0; h < H; h++) { m[h] = -1e30f; s[h] = 0.f; }
    for (int e = beg + lane; e < end; e += 32) {
        int src = g_col[e];
        const float4* ap4 = (const float4*)(asrc + (size_t)src * H);
        float av[H];
#pragma unroll
        for (int q = 0; q < H / 4; q++) {
            float4 t = ap4[q];
            av[4 * q] = t.x; av[4 * q + 1] = t.y; av[4 * q + 2] = t.z; av[4 * q + 3] = t.w;
        }
#pragma unroll
        for (int h = 0; h < H; h++) {
            float x = av[h] + ad[h];
            x = x > 0.f ? x : 0.2f * x;
            if (x > m[h]) {
                s[h] = s[h] * __expf(m[h] - x) + 1.f;
                m[h] = x;
            } else {
                s[h] += __expf(x - m[h]);
            }
        }
    }
    // merge lanes: global max, rescale sums, reduce
#pragma unroll
    for (int h = 0; h < H; h++) {
        float mw = m[h];
#pragma unroll
        for (int off = 16; off; off >>= 1)
            mw = fmaxf(mw, __shfl_xor_sync(0xffffffffu, mw, off));
        float sw = s[h] * __expf(m[h] - mw);
#pragma unroll
        for (int off = 16; off; off >>= 1)
            sw += __shfl_xor_sync(0xffffffffu, sw, off);
        m[h] = mw;
        s[h] = sw;
    }

    // pass B: weighted feature accumulation (branchless)
    float acc[H];
#pragma unroll
    for (int h = 0; h < H; h++) acc[h] = 0.f;
    for (int e = beg; e < end; e++) {
        int src = g_col[e];
        const float4* ap4 = (const float4*)(asrc + (size_t)src * H);
        const float*  hp  = hfeat + (size_t)src * (H * 32);
        float av[H];
#pragma unroll
        for (int q = 0; q < H / 4; q++) {
            float4 t = ap4[q];
            av[4 * q] = t.x; av[4 * q + 1] = t.y; av[4 * q + 2] = t.z; av[4 * q + 3] = t.w;
        }
#pragma unroll
        for (int h = 0; h < H; h++) {
            float x = av[h] + ad[h];
            x = x > 0.f ? x : 0.2f * x;
            float wt = __expf(x - m[h]);
            acc[h] += hp[h * 32 + lane] * wt;
        }
    }

    if (MEAN_OUT) {
        float v = 0.f;
#pragma unroll
        for (int h = 0; h < H; h++) v += acc[h] / s[h];
        out[(size_t)w * 32 + lane] = v * (1.f / H) + bias[lane];
    } else {
#pragma unroll
        for (int h = 0; h < H; h++) {
            float v = acc[h] / s[h] + bias[h * 32 + lane];
            if (ELU_OUT) v = v > 0.f ? v : expm1f(v);
            out[(size_t)w * (H * 32) + h * 32 + lane] = v;
        }
    }
}

// ---------------- launch ------------------------------------------------------
extern "C" void kernel_launch(void* const* d_in, const int* in_sizes, int n_in,
                              void* d_out, int out_size) {
    const float* x   = (const float*)d_in[0];
    const void*  ei  = d_in[1];
    const float* W1  = (const float*)d_in[2];
    const float* at_s1 = (const float*)d_in[3];
    const float* at_d1 = (const float*)d_in[4];
    const float* b1  = (const float*)d_in[5];
    const float* W2  = (const float*)d_in[6];
    const float* at_s2 = (const float*)d_in[7];
    const float* at_d2 = (const float*)d_in[8];
    const float* b2  = (const float*)d_in[9];
    float* out = (float*)d_out;

    float *h1, *h1a, *h2, *pas1, *pad1, *pas2, *pad2;
    cudaGetSymbolAddress((void**)&h1,  g_h1);
    cudaGetSymbolAddress((void**)&h1a, g_h1a);
    cudaGetSymbolAddress((void**)&h2,  g_h2);
    cudaGetSymbolAddress((void**)&pas1, g_as1);
    cudaGetSymbolAddress((void**)&pad1, g_ad1);
    cudaGetSymbolAddress((void**)&pas2, g_as2);
    cudaGetSymbolAddress((void**)&pad2, g_ad2);

    dim3 gemm_grid1(128 / SG_BN, (N_NODES + SG_BM - 1) / SG_BM);   // (1, 391)
    dim3 gemm_grid2(256 / SG_BN, (N_NODES + SG_BM - 1) / SG_BM);   // (2, 391)

    // CSR build interleaved with gemm1 so that gemm1 is launch #5 (0-indexed),
    // which is where the profiler's fixed -s 5 -c 1 window lands.
    detect64_kernel<<<1, 256>>>((const unsigned int*)ei);              // 0
    zero_cnt_kernel<<<(N_NODES + 255) / 256, 256>>>();                 // 1
    count_kernel<<<(E_TOT + 255) / 256, 256>>>(ei);                    // 2
    scan1_kernel<<<SCAN_NB, 1024>>>();                                 // 3
    scan2_kernel<<<1, 32>>>();                                         // 4
    sgemm128db_kernel<<<gemm_grid1, 256>>>(x, W1, h1, N_NODES, 128, 128); // 5 (profiled)
    scan3_kernel<<<(N_NODES + 255) / 256, 256>>>();                    // 6
    scatter_kernel<<<(E_TOT + 255) / 256, 256>>>(ei);                  // 7

    // layer 1 (gemm1 already issued above)
    alpha_kernel<4><<<(N_NODES * 4 + 255) / 256, 256>>>(h1, at_s1, at_d1, pas1, pad1);
    gat_edge_kernel<4, true, false><<<(N_NODES + 7) / 8, 256>>>(h1, pas1, pad1, b1, h1a);

    // layer 2
    sgemm128db_kernel<<<gemm_grid2, 256>>>(h1a, W2, h2, N_NODES, 256, 128);
    alpha_kernel<8><<<(N_NODES * 8 + 255) / 256, 256>>>(h2, at_s2, at_d2, pas2, pad2);
    gat_edge_kernel<8, false, true><<<(N_NODES + 7) / 8, 256>>>(h2, pas2, pad2, b2, out);
}

// round 10
// speedup vs baseline: 1.5238x; 1.1582x over previous
#include <cuda_runtime.h>
#include <cuda_fp16.h>
#include <math.h>

// Problem constants (fixed by the dataset)
#define N_NODES 50000
#define N_PAD   50048
#define E_EDGES 800000
#define E_TOT   (E_EDGES + N_NODES)
#define SCAN_NB ((N_NODES + 1023) / 1024)   // 49

// ---------------- scratch (static __device__ allocations only) ----------------
__device__ float  g_h1 [(size_t)N_PAD * 128];   // x @ W1            [N,4,32]
__device__ float  g_h1a[(size_t)N_PAD * 128];   // elu(gat1 output)  [N,128]
__device__ float  g_h2 [(size_t)N_PAD * 256];   // h1a @ W2          [N,8,32]
__device__ __half g_h16[(size_t)N_PAD * 256];   // fp16 copy of h for gathers
__device__ float  g_ew [(size_t)E_TOT * 8];     // per-edge normalized weights
__device__ float  g_as1[N_NODES * 4];
__device__ float  g_ad1[N_NODES * 4];
__device__ float  g_as2[N_NODES * 8];
__device__ float  g_ad2[N_NODES * 8];
__device__ int    g_cnt[N_NODES];
__device__ int    g_tmp[N_NODES];
__device__ int    g_bsum[SCAN_NB];
__device__ int    g_boff[SCAN_NB];
__device__ int    g_rowptr[N_NODES + 1];
__device__ int    g_cursor[N_NODES];
__device__ int    g_col[E_TOT];
__device__ int    g_is64;

// ---------------- dtype detection for edge_index (int64 vs int32) -------------
__global__ void detect64_kernel(const unsigned int* __restrict__ w) {
    __shared__ int any;
    if (threadIdx.x == 0) any = 0;
    __syncthreads();
    for (int i = 1 + 2 * threadIdx.x; i < 2048; i += 2 * blockDim.x)
        if (w[i] != 0u) any = 1;   // benign race
    __syncthreads();
    if (threadIdx.x == 0) g_is64 = (any == 0) ? 1 : 0;
}

__global__ void zero_cnt_kernel() {
    int i = blockIdx.x * blockDim.x + threadIdx.x;
    if (i < N_NODES) g_cnt[i] = 0;
}

__global__ void count_kernel(const void* __restrict__ ei) {
    int e = blockIdx.x * blockDim.x + threadIdx.x;
    if (e >= E_TOT) return;
    int dst;
    if (e < E_EDGES) {
        if (g_is64) dst = (int)((const long long*)ei)[(size_t)E_EDGES + e];
        else        dst = ((const int*)ei)[E_EDGES + e];
    } else {
        dst = e - E_EDGES;   // self loop
    }
    atomicAdd(&g_cnt[dst], 1);
}

// ---------------- multi-block scan (3 tiny kernels) ---------------------------
__global__ void scan1_kernel() {
    int b = blockIdx.x, tid = threadIdx.x;
    int i = b * 1024 + tid;
    int lane = tid & 31, wid = tid >> 5;
    int v = (i < N_NODES) ? g_cnt[i] : 0;
    int x = v;
#pragma unroll
    for (int off = 1; off < 32; off <<= 1) {
        int t = __shfl_up_sync(0xffffffffu, x, off);
        if (lane >= off) x += t;
    }
    __shared__ int wsum[32];
    if (lane == 31) wsum[wid] = x;
    __syncthreads();
    if (wid == 0) {
        int y = wsum[lane];
#pragma unroll
        for (int off = 1; off < 32; off <<= 1) {
            int t = __shfl_up_sync(0xffffffffu, y, off);
            if (lane >= off) y += t;
        }
        wsum[lane] = y;
    }
    __syncthreads();
    int incl = x + (wid ? wsum[wid - 1] : 0);
    if (i < N_NODES) g_tmp[i] = incl;
    if (tid == 1023) g_bsum[b] = incl;
}

__global__ void scan2_kernel() {
    if (threadIdx.x == 0) {
        int run = 0;
#pragma unroll 1
        for (int j = 0; j < SCAN_NB; j++) { g_boff[j] = run; run += g_bsum[j]; }
        g_rowptr[0] = 0;
    }
}

__global__ void scan3_kernel() {
    int i = blockIdx.x * blockDim.x + threadIdx.x;
    if (i >= N_NODES) return;
    int incl = g_tmp[i] + g_boff[i >> 10];
    g_rowptr[i + 1] = incl;
    g_cursor[i]     = incl - g_cnt[i];
}

__global__ void scatter_kernel(const void* __restrict__ ei) {
    int e = blockIdx.x * blockDim.x + threadIdx.x;
    if (e >= E_TOT) return;
    int src, dst;
    if (e < E_EDGES) {
        if (g_is64) {
            const long long* p = (const long long*)ei;
            src = (int)p[e];
            dst = (int)p[(size_t)E_EDGES + e];
        } else {
            const int* p = (const int*)ei;
            src = p[e];
            dst = p[E_EDGES + e];
        }
    } else {
        src = dst = e - E_EDGES;
    }
    int pos = atomicAdd(&g_cursor[dst], 1);
    g_col[pos] = src;
}

// ---------------- SGEMM (R4-measured-good): 64x64 tile, 4x4/thread, BK=16 -----
#define BM 64
#define BN 64
#define BK 16
__global__ void sgemm_kernel(const float* __restrict__ A,
                             const float* __restrict__ B,
                             float* __restrict__ C,
                             int M, int Ncols, int K) {
    __shared__ float As[BK][BM];
    __shared__ float Bs[BK][BN];
    int tid = threadIdx.x;
    int row0 = blockIdx.y * BM;
    int col0 = blockIdx.x * BN;
    int ty = tid / 16, tx = tid % 16;

    int arow = tid / 4;
    int acol = (tid % 4) * 4;
    int brw  = tid / 16;
    int bcl  = (tid % 16) * 4;

    float acc[4][4];
#pragma unroll
    for (int i = 0; i < 4; i++)
#pragma unroll
        for (int j = 0; j < 4; j++) acc[i][j] = 0.f;

    for (int k0 = 0; k0 < K; k0 += BK) {
        float4 av = make_float4(0.f, 0.f, 0.f, 0.f);
        if (row0 + arow < M)
            av = *(const float4*)(A + (size_t)(row0 + arow) * K + k0 + acol);
        As[acol + 0][arow] = av.x;
        As[acol + 1][arow] = av.y;
        As[acol + 2][arow] = av.z;
        As[acol + 3][arow] = av.w;
        float4 bv = *(const float4*)(B + (size_t)(k0 + brw) * Ncols + col0 + bcl);
        *(float4*)&Bs[brw][bcl] = bv;
        __syncthreads();
#pragma unroll
        for (int kk = 0; kk < BK; kk++) {
            float4 a = *(float4*)&As[kk][ty * 4];
            float4 b = *(float4*)&Bs[kk][tx * 4];
            acc[0][0] += a.x * b.x; acc[0][1] += a.x * b.y; acc[0][2] += a.x * b.z; acc[0][3] += a.x * b.w;
            acc[1][0] += a.y * b.x; acc[1][1] += a.y * b.y; acc[1][2] += a.y * b.z; acc[1][3] += a.y * b.w;
            acc[2][0] += a.z * b.x; acc[2][1] += a.z * b.y; acc[2][2] += a.z * b.z; acc[2][3] += a.z * b.w;
            acc[3][0] += a.w * b.x; acc[3][1] += a.w * b.y; acc[3][2] += a.w * b.z; acc[3][3] += a.w * b.w;
        }
        __syncthreads();
    }
#pragma unroll
    for (int i = 0; i < 4; i++) {
        int r = row0 + ty * 4 + i;
        if (r < M)
            *(float4*)(C + (size_t)r * Ncols + col0 + tx * 4) =
                make_float4(acc[i][0], acc[i][1], acc[i][2], acc[i][3]);
    }
}

// ------- per-node attention coefficients + fp16 feature copy (fused) ----------
template <int H>
__global__ void alpha_h16_kernel(const float* __restrict__ h,
                                 const float* __restrict__ att_s,
                                 const float* __restrict__ att_d,
                                 float* __restrict__ as_out,
                                 float* __restrict__ ad_out) {
    int idx = blockIdx.x * blockDim.x + threadIdx.x;
    if (idx >= N_NODES * H) return;
    int node = idx / H, hh = idx % H;
    const float* hp = h + (size_t)node * H * 32 + hh * 32;
    const float* a1 = att_s + hh * 32;
    const float* a2 = att_d + hh * 32;
    __half* h16p = g_h16 + (size_t)node * H * 32 + hh * 32;
    float s1 = 0.f, s2 = 0.f;
#pragma unroll
    for (int c = 0; c < 32; c += 4) {
        float4 v  = *(const float4*)(hp + c);
        float4 w1 = *(const float4*)(a1 + c);
        float4 w2 = *(const float4*)(a2 + c);
        s1 += v.x * w1.x + v.y * w1.y + v.z * w1.z + v.w * w1.w;
        s2 += v.x * w2.x + v.y * w2.y + v.z * w2.z + v.w * w2.w;
        __half2 p0 = __floats2half2_rn(v.x, v.y);
        __half2 p1 = __floats2half2_rn(v.z, v.w);
        *(__half2*)(h16p + c)     = p0;
        *(__half2*)(h16p + c + 2) = p1;
    }
    as_out[idx] = s1;
    ad_out[idx] = s2;
}

// ------- stats + per-edge weight precompute: one warp per destination node ----
// Pass A: lane-parallel online softmax (as R4). Then a second lane-parallel
// sweep writes w[e,h] = exp(x - m) * (1/s) to g_ew (coalesced stores).
template <int H>
__global__ void stats_kernel(const float* __restrict__ asrc,
                             const float* __restrict__ adst) {
    int w    = (blockIdx.x * blockDim.x + threadIdx.x) >> 5;
    int lane = threadIdx.x & 31;
    if (w >= N_NODES) return;
    int beg = g_rowptr[w], end = g_rowptr[w + 1];

    float ad[H];
#pragma unroll
    for (int h = 0; h < H; h++) ad[h] = adst[(size_t)w * H + h];

    float m[H], s[H];
#pragma unroll
    for (int h = 0; h < H; h++) { m[h] = -1e30f; s[h] = 0.f; }
    for (int e = beg + lane; e < end; e += 32) {
        int src = g_col[e];
        const float4* ap4 = (const float4*)(asrc + (size_t)src * H);
        float av[H];
#pragma unroll
        for (int q = 0; q < H / 4; q++) {
            float4 t = ap4[q];
            av[4 * q] = t.x; av[4 * q + 1] = t.y; av[4 * q + 2] = t.z; av[4 * q + 3] = t.w;
        }
#pragma unroll
        for (int h = 0; h < H; h++) {
            float x = av[h] + ad[h];
            x = x > 0.f ? x : 0.2f * x;
            if (x > m[h]) {
                s[h] = s[h] * __expf(m[h] - x) + 1.f;
                m[h] = x;
            } else {
                s[h] += __expf(x - m[h]);
            }
        }
    }
#pragma unroll
    for (int h = 0; h < H; h++) {
        float mw = m[h];
#pragma unroll
        for (int off = 16; off; off >>= 1)
            mw = fmaxf(mw, __shfl_xor_sync(0xffffffffu, mw, off));
        float sw = s[h] * __expf(m[h] - mw);
#pragma unroll
        for (int off = 16; off; off >>= 1)
            sw += __shfl_xor_sync(0xffffffffu, sw, off);
        m[h] = mw;
        s[h] = 1.f / sw;     // inv_s
    }

    // weight sweep: lane-parallel, coalesced float4 stores
    for (int e = beg + lane; e < end; e += 32) {
        int src = g_col[e];
        const float4* ap4 = (const float4*)(asrc + (size_t)src * H);
        float av[H], wv[H];
#pragma unroll
        for (int q = 0; q < H / 4; q++) {
            float4 t = ap4[q];
            av[4 * q] = t.x; av[4 * q + 1] = t.y; av[4 * q + 2] = t.z; av[4 * q + 3] = t.w;
        }
#pragma unroll
        for (int h = 0; h < H; h++) {
            float x = av[h] + ad[h];
            x = x > 0.f ? x : 0.2f * x;
            wv[h] = __expf(x - m[h]) * s[h];
        }
        float4* wp = (float4*)(g_ew + (size_t)e * H);
#pragma unroll
        for (int q = 0; q < H / 4; q++)
            wp[q] = make_float4(wv[4 * q], wv[4 * q + 1], wv[4 * q + 2], wv[4 * q + 3]);
    }
}

// ------- aggregation: one warp per node, fp16 feature gathers, fp32 accum -----
// Layer 1 (H=4, concat+ELU): lane L owns channels 4L..4L+3 (head L/8).
//   per edge: 1 LDG.64 (8B fp16) + 1 LDG.32 (weight) + 4 FFMA.
__global__ void agg1_kernel(const float* __restrict__ bias,
                            float* __restrict__ out) {
    int w    = (blockIdx.x * blockDim.x + threadIdx.x) >> 5;
    int lane = threadIdx.x & 31;
    if (w >= N_NODES) return;
    int beg = g_rowptr[w], end = g_rowptr[w + 1];
    int hsel = lane >> 3;                 // head this lane accumulates

    float acc[4] = {0.f, 0.f, 0.f, 0.f};
    for (int e = beg; e < end; e++) {
        int src = g_col[e];                                   // broadcast
        float wt = g_ew[(size_t)e * 4 + hsel];                // per-lane scalar
        uint2 hv = *((const uint2*)(g_h16 + (size_t)src * 128) + lane);  // 8B/lane
        __half2 p0 = *(__half2*)&hv.x;
        __half2 p1 = *(__half2*)&hv.y;
        float2 f0 = __half22float2(p0);
        float2 f1 = __half22float2(p1);
        acc[0] += f0.x * wt;
        acc[1] += f0.y * wt;
        acc[2] += f1.x * wt;
        acc[3] += f1.y * wt;
    }
    float4 bv = *((const float4*)bias + lane);
    float4 o;
    o.x = acc[0] + bv.x; o.y = acc[1] + bv.y; o.z = acc[2] + bv.z; o.w = acc[3] + bv.w;
    o.x = o.x > 0.f ? o.x : expm1f(o.x);
    o.y = o.y > 0.f ? o.y : expm1f(o.y);
    o.z = o.z > 0.f ? o.z : expm1f(o.z);
    o.w = o.w > 0.f ? o.w : expm1f(o.w);
    *((float4*)(out + (size_t)w * 128) + lane) = o;
}

// Layer 2 (H=8, mean over heads): lane L owns channels 8L..8L+7 (head L/4,
// c-base (L%4)*8). per edge: 1 LDG.128 + 1 LDG.32 + 8 FFMA. Head-mean via
// 3-round shuffle reduction over lanes sharing L%4.
__global__ void agg2_kernel(const float* __restrict__ bias,
                            float* __restrict__ out) {
    int w    = (blockIdx.x * blockDim.x + threadIdx.x) >> 5;
    int lane = threadIdx.x & 31;
    if (w >= N_NODES) return;
    int beg = g_rowptr[w], end = g_rowptr[w + 1];
    int hsel = lane >> 2;

    float acc[8];
#pragma unroll
    for (int j = 0; j < 8; j++) acc[j] = 0.f;

    for (int e = beg; e < end; e++) {
        int src = g_col[e];
        float wt = g_ew[(size_t)e * 8 + hsel];
        uint4 hv = *((const uint4*)(g_h16 + (size_t)src * 256) + lane);  // 16B/lane
        float2 f0 = __half22float2(*(__half2*)&hv.x);
        float2 f1 = __half22float2(*(__half2*)&hv.y);
        float2 f2 = __half22float2(*(__half2*)&hv.z);
        float2 f3 = __half22float2(*(__half2*)&hv.w);
        acc[0] += f0.x * wt; acc[1] += f0.y * wt;
        acc[2] += f1.x * wt; acc[3] += f1.y * wt;
        acc[4] += f2.x * wt; acc[5] += f2.y * wt;
        acc[6] += f3.x * wt; acc[7] += f3.y * wt;
    }
    // reduce over heads: lanes {L, L^4, L^8, ...} share the same channel block
#pragma unroll
    for (int off = 4; off < 32; off <<= 1)
#pragma unroll
        for (int j = 0; j < 8; j++)
            acc[j] += __shfl_xor_sync(0xffffffffu, acc[j], off);

    if (lane < 4) {
        int c0 = lane * 8;
        float4 b0 = *(const float4*)(bias + c0);
        float4 b1 = *(const float4*)(bias + c0 + 4);
        float4 o0, o1;
        o0.x = acc[0] * 0.125f + b0.x; o0.y = acc[1] * 0.125f + b0.y;
        o0.z = acc[2] * 0.125f + b0.z; o0.w = acc[3] * 0.125f + b0.w;
        o1.x = acc[4] * 0.125f + b1.x; o1.y = acc[5] * 0.125f + b1.y;
        o1.z = acc[6] * 0.125f + b1.z; o1.w = acc[7] * 0.125f + b1.w;
        *(float4*)(out + (size_t)w * 32 + c0)     = o0;
        *(float4*)(out + (size_t)w * 32 + c0 + 4) = o1;
    }
}

// ---------------- launch ------------------------------------------------------
extern "C" void kernel_launch(void* const* d_in, const int* in_sizes, int n_in,
                              void* d_out, int out_size) {
    const float* x   = (const float*)d_in[0];
    const void*  ei  = d_in[1];
    const float* W1  = (const float*)d_in[2];
    const float* at_s1 = (const float*)d_in[3];
    const float* at_d1 = (const float*)d_in[4];
    const float* b1  = (const float*)d_in[5];
    const float* W2  = (const float*)d_in[6];
    const float* at_s2 = (const float*)d_in[7];
    const float* at_d2 = (const float*)d_in[8];
    const float* b2  = (const float*)d_in[9];
    float* out = (float*)d_out;

    float *h1, *h1a, *h2, *pas1, *pad1, *pas2, *pad2;
    cudaGetSymbolAddress((void**)&h1,  g_h1);
    cudaGetSymbolAddress((void**)&h1a, g_h1a);
    cudaGetSymbolAddress((void**)&h2,  g_h2);
    cudaGetSymbolAddress((void**)&pas1, g_as1);
    cudaGetSymbolAddress((void**)&pad1, g_ad1);
    cudaGetSymbolAddress((void**)&pas2, g_as2);
    cudaGetSymbolAddress((void**)&pad2, g_ad2);

    // CSR build; gemm1 interleaved (independent of CSR)
    detect64_kernel<<<1, 256>>>((const unsigned int*)ei);
    zero_cnt_kernel<<<(N_NODES + 255) / 256, 256>>>();
    count_kernel<<<(E_TOT + 255) / 256, 256>>>(ei);
    scan1_kernel<<<SCAN_NB, 1024>>>();
    scan2_kernel<<<1, 32>>>();
    {
        dim3 grid(128 / BN, (N_NODES + BM - 1) / BM);
        sgemm_kernel<<<grid, 256>>>(x, W1, h1, N_NODES, 128, 128);
    }
    scan3_kernel<<<(N_NODES + 255) / 256, 256>>>();
    scatter_kernel<<<(E_TOT + 255) / 256, 256>>>(ei);

    // layer 1
    alpha_h16_kernel<4><<<(N_NODES * 4 + 255) / 256, 256>>>(h1, at_s1, at_d1, pas1, pad1);
    stats_kernel<4><<<(N_NODES + 7) / 8, 256>>>(pas1, pad1);
    agg1_kernel<<<(N_NODES + 7) / 8, 256>>>(b1, h1a);

    // layer 2
    {
        dim3 grid(256 / BN, (N_NODES + BM - 1) / BM);
        sgemm_kernel<<<grid, 256>>>(h1a, W2, h2, N_NODES, 256, 128);
    }
    alpha_h16_kernel<8><<<(N_NODES * 8 + 255) / 256, 256>>>(h2, at_s2, at_d2, pas2, pad2);
    stats_kernel<8><<<(N_NODES + 7) / 8, 256>>>(pas2, pad2);
    agg2_kernel<<<(N_NODES + 7) / 8, 256>>>(b2, out);
}

// round 11
// speedup vs baseline: 2.0352x; 1.3356x over previous
#include <cuda_runtime.h>
#include <cuda_fp16.h>
#include <math.h>
#include <mma.h>

using namespace nvcuda;

// Problem constants (fixed by the dataset)
#define N_NODES 50000
#define N_PAD   50048                        // 391 * 128
#define E_EDGES 800000
#define E_TOT   (E_EDGES + N_NODES)
#define SCAN_NB ((N_NODES + 1023) / 1024)   // 49

// ---------------- scratch (static __device__ allocations only) ----------------
__device__ float  g_h1 [(size_t)N_PAD * 128];   // hgemm1 out        [N,4,32] fp32
__device__ float  g_h2 [(size_t)N_PAD * 256];   // hgemm2 out        [N,8,32] fp32
__device__ __half g_x16[(size_t)N_PAD * 128];   // fp16 copy of x
__device__ __half g_h1a16[(size_t)N_PAD * 128]; // elu(gat1) fp16 (gemm2 input)
__device__ __half g_h16[(size_t)N_PAD * 256];   // fp16 copy of h for gathers
__device__ __half g_w1h[128 * 128];
__device__ __half g_w2h[128 * 256];
__device__ float  g_ew [(size_t)E_TOT * 8];     // per-edge normalized weights
__device__ float  g_as1[N_NODES * 4];
__device__ float  g_ad1[N_NODES * 4];
__device__ float  g_as2[N_NODES * 8];
__device__ float  g_ad2[N_NODES * 8];
__device__ int    g_cnt[N_NODES];
__device__ int    g_tmp[N_NODES];
__device__ int    g_bsum[SCAN_NB];
__device__ int    g_boff[SCAN_NB];
__device__ int    g_rowptr[N_NODES + 1];
__device__ int    g_cursor[N_NODES];
__device__ int    g_col[E_TOT];
__device__ int    g_is64;

// ---------------- dtype detection for edge_index (int64 vs int32) -------------
__global__ void detect64_kernel(const unsigned int* __restrict__ w) {
    __shared__ int any;
    if (threadIdx.x == 0) any = 0;
    __syncthreads();
    for (int i = 1 + 2 * threadIdx.x; i < 2048; i += 2 * blockDim.x)
        if (w[i] != 0u) any = 1;   // benign race
    __syncthreads();
    if (threadIdx.x == 0) g_is64 = (any == 0) ? 1 : 0;
}

__global__ void zero_cnt_kernel() {
    int i = blockIdx.x * blockDim.x + threadIdx.x;
    if (i < N_NODES) g_cnt[i] = 0;
}

__global__ void count_kernel(const void* __restrict__ ei) {
    int e = blockIdx.x * blockDim.x + threadIdx.x;
    if (e >= E_TOT) return;
    int dst;
    if (e < E_EDGES) {
        if (g_is64) dst = (int)((const long long*)ei)[(size_t)E_EDGES + e];
        else        dst = ((const int*)ei)[E_EDGES + e];
    } else {
        dst = e - E_EDGES;   // self loop
    }
    atomicAdd(&g_cnt[dst], 1);
}

// ---------------- multi-block scan (3 tiny kernels) ---------------------------
__global__ void scan1_kernel() {
    int b = blockIdx.x, tid = threadIdx.x;
    int i = b * 1024 + tid;
    int lane = tid & 31, wid = tid >> 5;
    int v = (i < N_NODES) ? g_cnt[i] : 0;
    int x = v;
#pragma unroll
    for (int off = 1; off < 32; off <<= 1) {
        int t = __shfl_up_sync(0xffffffffu, x, off);
        if (lane >= off) x += t;
    }
    __shared__ int wsum[32];
    if (lane == 31) wsum[wid] = x;
    __syncthreads();
    if (wid == 0) {
        int y = wsum[lane];
#pragma unroll
        for (int off = 1; off < 32; off <<= 1) {
            int t = __shfl_up_sync(0xffffffffu, y, off);
            if (lane >= off) y += t;
        }
        wsum[lane] = y;
    }
    __syncthreads();
    int incl = x + (wid ? wsum[wid - 1] : 0);
    if (i < N_NODES) g_tmp[i] = incl;
    if (tid == 1023) g_bsum[b] = incl;
}

__global__ void scan2_kernel() {
    if (threadIdx.x == 0) {
        int run = 0;
#pragma unroll 1
        for (int j = 0; j < SCAN_NB; j++) { g_boff[j] = run; run += g_bsum[j]; }
        g_rowptr[0] = 0;
    }
}

__global__ void scan3_kernel() {
    int i = blockIdx.x * blockDim.x + threadIdx.x;
    if (i >= N_NODES) return;
    int incl = g_tmp[i] + g_boff[i >> 10];
    g_rowptr[i + 1] = incl;
    g_cursor[i]     = incl - g_cnt[i];
}

__global__ void scatter_kernel(const void* __restrict__ ei) {
    int e = blockIdx.x * blockDim.x + threadIdx.x;
    if (e >= E_TOT) return;
    int src, dst;
    if (e < E_EDGES) {
        if (g_is64) {
            const long long* p = (const long long*)ei;
            src = (int)p[e];
            dst = (int)p[(size_t)E_EDGES + e];
        } else {
            const int* p = (const int*)ei;
            src = p[e];
            dst = p[E_EDGES + e];
        }
    } else {
        src = dst = e - E_EDGES;
    }
    int pos = atomicAdd(&g_cursor[dst], 1);
    g_col[pos] = src;
}

// ---------------- fp32 -> fp16 conversions ------------------------------------
__global__ void convx_kernel(const float* __restrict__ x) {
    int i = blockIdx.x * blockDim.x + threadIdx.x;
    if (i >= N_NODES * 32) return;             // 128/4 float4s per row
    float4 v = ((const float4*)x)[i];
    __half2 p0 = __floats2half2_rn(v.x, v.y);
    __half2 p1 = __floats2half2_rn(v.z, v.w);
    ((__half2*)g_x16)[2 * i]     = p0;
    ((__half2*)g_x16)[2 * i + 1] = p1;
}

__global__ void convw_kernel(const float* __restrict__ W1,
                             const float* __restrict__ W2) {
    int i = blockIdx.x * blockDim.x + threadIdx.x;
    if (i < 4096) {                             // W1: 16384 floats
        float4 v = ((const float4*)W1)[i];
        ((__half2*)g_w1h)[2 * i]     = __floats2half2_rn(v.x, v.y);
        ((__half2*)g_w1h)[2 * i + 1] = __floats2half2_rn(v.z, v.w);
    } else if (i < 4096 + 8192) {               // W2: 32768 floats
        int j = i - 4096;
        float4 v = ((const float4*)W2)[j];
        ((__half2*)g_w2h)[2 * j]     = __floats2half2_rn(v.x, v.y);
        ((__half2*)g_w2h)[2 * j + 1] = __floats2half2_rn(v.z, v.w);
    }
}

// ---------------- fp16 tensor-core GEMM: C[M_pad,N] = A[M_pad,K] @ B[K,N] -----
// Block 128x64, 8 warps (4x2), warp tile 32x32, BK=32, m16n16k16 HMMA,
// fp32 accumulate. No per-fragment conversion (operands already fp16).
#define HG_BM 128
#define HG_BN 64
#define HG_BK 32
#define HLDA 40
#define HLDB 72

__global__ void hgemm_kernel(const __half* __restrict__ A,
                             const __half* __restrict__ B,
                             float* __restrict__ C,
                             int N, int K) {
    __shared__ __half Ah[HG_BM * HLDA];
    __shared__ __half Bh[HG_BK * HLDB];
    int tid = threadIdx.x;
    int wid = tid >> 5;
    int wm = wid & 3, wn = wid >> 2;
    size_t row0 = (size_t)blockIdx.y * HG_BM;
    int col0 = blockIdx.x * HG_BN;

    wmma::fragment<wmma::accumulator, 16, 16, 16, float> c[2][2];
#pragma unroll
    for (int i = 0; i < 2; i++)
#pragma unroll
        for (int j = 0; j < 2; j++) wmma::fill_fragment(c[i][j], 0.f);

    for (int k0 = 0; k0 < K; k0 += HG_BK) {
        // A tile: 128x32 halves = 512 uint4; 2 per thread
#pragma unroll
        for (int i = 0; i < 2; i++) {
            int f = tid + i * 256;
            int r = f >> 2, cc = (f & 3) * 8;
            *(uint4*)(Ah + r * HLDA + cc) =
                *(const uint4*)(A + (row0 + r) * K + k0 + cc);
        }
        // B tile: 32x64 halves = 256 uint4; 1 per thread
        {
            int r = tid >> 3, cc = (tid & 7) * 8;
            *(uint4*)(Bh + r * HLDB + cc) =
                *(const uint4*)(B + (size_t)(k0 + r) * N + col0 + cc);
        }
        __syncthreads();
#pragma unroll
        for (int kk = 0; kk < HG_BK; kk += 16) {
            wmma::fragment<wmma::matrix_a, 16, 16, 16, __half, wmma::row_major> a[2];
            wmma::fragment<wmma::matrix_b, 16, 16, 16, __half, wmma::row_major> b[2];
#pragma unroll
            for (int mi = 0; mi < 2; mi++)
                wmma::load_matrix_sync(a[mi], Ah + (wm * 32 + mi * 16) * HLDA + kk, HLDA);
#pragma unroll
            for (int ni = 0; ni < 2; ni++)
                wmma::load_matrix_sync(b[ni], Bh + kk * HLDB + wn * 32 + ni * 16, HLDB);
#pragma unroll
            for (int mi = 0; mi < 2; mi++)
#pragma unroll
                for (int ni = 0; ni < 2; ni++)
                    wmma::mma_sync(c[mi][ni], a[mi], b[ni], c[mi][ni]);
        }
        __syncthreads();
    }
#pragma unroll
    for (int mi = 0; mi < 2; mi++)
#pragma unroll
        for (int ni = 0; ni < 2; ni++)
            wmma::store_matrix_sync(
                C + (row0 + wm * 32 + mi * 16) * N + col0 + wn * 32 + ni * 16,
                c[mi][ni], N, wmma::mem_row_major);
}

// ------- per-node attention coefficients + fp16 feature copy (fused) ----------
template <int H>
__global__ void alpha_h16_kernel(const float* __restrict__ h,
                                 const float* __restrict__ att_s,
                                 const float* __restrict__ att_d,
                                 float* __restrict__ as_out,
                                 float* __restrict__ ad_out) {
    int idx = blockIdx.x * blockDim.x + threadIdx.x;
    if (idx >= N_NODES * H) return;
    int node = idx / H, hh = idx % H;
    const float* hp = h + (size_t)node * H * 32 + hh * 32;
    const float* a1 = att_s + hh * 32;
    const float* a2 = att_d + hh * 32;
    __half* h16p = g_h16 + (size_t)node * H * 32 + hh * 32;
    float s1 = 0.f, s2 = 0.f;
#pragma unroll
    for (int c = 0; c < 32; c += 4) {
        float4 v  = *(const float4*)(hp + c);
        float4 w1 = *(const float4*)(a1 + c);
        float4 w2 = *(const float4*)(a2 + c);
        s1 += v.x * w1.x + v.y * w1.y + v.z * w1.z + v.w * w1.w;
        s2 += v.x * w2.x + v.y * w2.y + v.z * w2.z + v.w * w2.w;
        *(__half2*)(h16p + c)     = __floats2half2_rn(v.x, v.y);
        *(__half2*)(h16p + c + 2) = __floats2half2_rn(v.z, v.w);
    }
    as_out[idx] = s1;
    ad_out[idx] = s2;
}

// ------- stats + per-edge weight precompute: one warp per destination node ----
template <int H>
__global__ void stats_kernel(const float* __restrict__ asrc,
                             const float* __restrict__ adst) {
    int w    = (blockIdx.x * blockDim.x + threadIdx.x) >> 5;
    int lane = threadIdx.x & 31;
    if (w >= N_NODES) return;
    int beg = g_rowptr[w], end = g_rowptr[w + 1];

    float ad[H];
#pragma unroll
    for (int h = 0; h < H; h++) ad[h] = adst[(size_t)w * H + h];

    float m[H], s[H];
#pragma unroll
    for (int h = 0; h < H; h++) { m[h] = -1e30f; s[h] = 0.f; }
    for (int e = beg + lane; e < end; e += 32) {
        int src = g_col[e];
        const float4* ap4 = (const float4*)(asrc + (size_t)src * H);
        float av[H];
#pragma unroll
        for (int q = 0; q < H / 4; q++) {
            float4 t = ap4[q];
            av[4 * q] = t.x; av[4 * q + 1] = t.y; av[4 * q + 2] = t.z; av[4 * q + 3] = t.w;
        }
#pragma unroll
        for (int h = 0; h < H; h++) {
            float x = av[h] + ad[h];
            x = x > 0.f ? x : 0.2f * x;
            if (x > m[h]) {
                s[h] = s[h] * __expf(m[h] - x) + 1.f;
                m[h] = x;
            } else {
                s[h] += __expf(x - m[h]);
            }
        }
    }
#pragma unroll
    for (int h = 0; h < H; h++) {
        float mw = m[h];
#pragma unroll
        for (int off = 16; off; off >>= 1)
            mw = fmaxf(mw, __shfl_xor_sync(0xffffffffu, mw, off));
        float sw = s[h] * __expf(m[h] - mw);
#pragma unroll
        for (int off = 16; off; off >>= 1)
            sw += __shfl_xor_sync(0xffffffffu, sw, off);
        m[h] = mw;
        s[h] = 1.f / sw;     // inv_s
    }

    for (int e = beg + lane; e < end; e += 32) {
        int src = g_col[e];
        const float4* ap4 = (const float4*)(asrc + (size_t)src * H);
        float av[H], wv[H];
#pragma unroll
        for (int q = 0; q < H / 4; q++) {
            float4 t = ap4[q];
            av[4 * q] = t.x; av[4 * q + 1] = t.y; av[4 * q + 2] = t.z; av[4 * q + 3] = t.w;
        }
#pragma unroll
        for (int h = 0; h < H; h++) {
            float x = av[h] + ad[h];
            x = x > 0.f ? x : 0.2f * x;
            wv[h] = __expf(x - m[h]) * s[h];
        }
        float4* wp = (float4*)(g_ew + (size_t)e * H);
#pragma unroll
        for (int q = 0; q < H / 4; q++)
            wp[q] = make_float4(wv[4 * q], wv[4 * q + 1], wv[4 * q + 2], wv[4 * q + 3]);
    }
}

// ------- aggregation: one warp per node, fp16 gathers, fp32 accum -------------
// Layer 1 (H=4, concat+ELU): writes fp16 h1a directly (gemm2 input).
__global__ void agg1_kernel(const float* __restrict__ bias) {
    int w    = (blockIdx.x * blockDim.x + threadIdx.x) >> 5;
    int lane = threadIdx.x & 31;
    if (w >= N_NODES) return;
    int beg = g_rowptr[w], end = g_rowptr[w + 1];
    int hsel = lane >> 3;

    float acc[4] = {0.f, 0.f, 0.f, 0.f};
    for (int e = beg; e < end; e++) {
        int src = g_col[e];
        float wt = g_ew[(size_t)e * 4 + hsel];
        uint2 hv = *((const uint2*)(g_h16 + (size_t)src * 128) + lane);
        float2 f0 = __half22float2(*(__half2*)&hv.x);
        float2 f1 = __half22float2(*(__half2*)&hv.y);
        acc[0] += f0.x * wt;
        acc[1] += f0.y * wt;
        acc[2] += f1.x * wt;
        acc[3] += f1.y * wt;
    }
    float4 bv = *((const float4*)bias + lane);
    float4 o;
    o.x = acc[0] + bv.x; o.y = acc[1] + bv.y; o.z = acc[2] + bv.z; o.w = acc[3] + bv.w;
    o.x = o.x > 0.f ? o.x : expm1f(o.x);
    o.y = o.y > 0.f ? o.y : expm1f(o.y);
    o.z = o.z > 0.f ? o.z : expm1f(o.z);
    o.w = o.w > 0.f ? o.w : expm1f(o.w);
    uint2 o16;
    *(__half2*)&o16.x = __floats2half2_rn(o.x, o.y);
    *(__half2*)&o16.y = __floats2half2_rn(o.z, o.w);
    ((uint2*)(g_h1a16 + (size_t)w * 128))[lane] = o16;
}

// Layer 2 (H=8, mean over heads).
__global__ void agg2_kernel(const float* __restrict__ bias,
                            float* __restrict__ out) {
    int w    = (blockIdx.x * blockDim.x + threadIdx.x) >> 5;
    int lane = threadIdx.x & 31;
    if (w >= N_NODES) return;
    int beg = g_rowptr[w], end = g_rowptr[w + 1];
    int hsel = lane >> 2;

    float acc[8];
#pragma unroll
    for (int j = 0; j < 8; j++) acc[j] = 0.f;

    for (int e = beg; e < end; e++) {
        int src = g_col[e];
        float wt = g_ew[(size_t)e * 8 + hsel];
        uint4 hv = *((const uint4*)(g_h16 + (size_t)src * 256) + lane);
        float2 f0 = __half22float2(*(__half2*)&hv.x);
        float2 f1 = __half22float2(*(__half2*)&hv.y);
        float2 f2 = __half22float2(*(__half2*)&hv.z);
        float2 f3 = __half22float2(*(__half2*)&hv.w);
        acc[0] += f0.x * wt; acc[1] += f0.y * wt;
        acc[2] += f1.x * wt; acc[3] += f1.y * wt;
        acc[4] += f2.x * wt; acc[5] += f2.y * wt;
        acc[6] += f3.x * wt; acc[7] += f3.y * wt;
    }
#pragma unroll
    for (int off = 4; off < 32; off <<= 1)
#pragma unroll
        for (int j = 0; j < 8; j++)
            acc[j] += __shfl_xor_sync(0xffffffffu, acc[j], off);

    if (lane < 4) {
        int c0 = lane * 8;
        float4 b0 = *(const float4*)(bias + c0);
        float4 b1 = *(const float4*)(bias + c0 + 4);
        float4 o0, o1;
        o0.x = acc[0] * 0.125f + b0.x; o0.y = acc[1] * 0.125f + b0.y;
        o0.z = acc[2] * 0.125f + b0.z; o0.w = acc[3] * 0.125f + b0.w;
        o1.x = acc[4] * 0.125f + b1.x; o1.y = acc[5] * 0.125f + b1.y;
        o1.z = acc[6] * 0.125f + b1.z; o1.w = acc[7] * 0.125f + b1.w;
        *(float4*)(out + (size_t)w * 32 + c0)     = o0;
        *(float4*)(out + (size_t)w * 32 + c0 + 4) = o1;
    }
}

// ---------------- launch ------------------------------------------------------
extern "C" void kernel_launch(void* const* d_in, const int* in_sizes, int n_in,
                              void* d_out, int out_size) {
    const float* x   = (const float*)d_in[0];
    const void*  ei  = d_in[1];
    const float* W1  = (const float*)d_in[2];
    const float* at_s1 = (const float*)d_in[3];
    const float* at_d1 = (const float*)d_in[4];
    const float* b1  = (const float*)d_in[5];
    const float* W2  = (const float*)d_in[6];
    const float* at_s2 = (const float*)d_in[7];
    const float* at_d2 = (const float*)d_in[8];
    const float* b2  = (const float*)d_in[9];
    float* out = (float*)d_out;

    float *h1, *h2, *pas1, *pad1, *pas2, *pad2;
    __half *x16, *w1h, *w2h, *h1a16;
    cudaGetSymbolAddress((void**)&h1,  g_h1);
    cudaGetSymbolAddress((void**)&h2,  g_h2);
    cudaGetSymbolAddress((void**)&x16, g_x16);
    cudaGetSymbolAddress((void**)&w1h, g_w1h);
    cudaGetSymbolAddress((void**)&w2h, g_w2h);
    cudaGetSymbolAddress((void**)&h1a16, g_h1a16);
    cudaGetSymbolAddress((void**)&pas1, g_as1);
    cudaGetSymbolAddress((void**)&pad1, g_ad1);
    cudaGetSymbolAddress((void**)&pas2, g_as2);
    cudaGetSymbolAddress((void**)&pad2, g_ad2);

    // CSR build + fp16 conversions (conversions independent of CSR)
    detect64_kernel<<<1, 256>>>((const unsigned int*)ei);
    zero_cnt_kernel<<<(N_NODES + 255) / 256, 256>>>();
    count_kernel<<<(E_TOT + 255) / 256, 256>>>(ei);
    convx_kernel<<<(N_NODES * 32 + 255) / 256, 256>>>(x);
    convw_kernel<<<(12288 + 255) / 256, 256>>>(W1, W2);
    scan1_kernel<<<SCAN_NB, 1024>>>();
    scan2_kernel<<<1, 32>>>();
    scan3_kernel<<<(N_NODES + 255) / 256, 256>>>();
    scatter_kernel<<<(E_TOT + 255) / 256, 256>>>(ei);

    dim3 hg1(128 / HG_BN, N_PAD / HG_BM);   // (2, 391)
    dim3 hg2(256 / HG_BN, N_PAD / HG_BM);   // (4, 391)

    // layer 1
    hgemm_kernel<<<hg1, 256>>>(x16, w1h, h1, 128, 128);
    alpha_h16_kernel<4><<<(N_NODES * 4 + 255) / 256, 256>>>(h1, at_s1, at_d1, pas1, pad1);
    stats_kernel<4><<<(N_NODES + 7) / 8, 256>>>(pas1, pad1);
    agg1_kernel<<<(N_NODES + 7) / 8, 256>>>(b1);

    // layer 2
    hgemm_kernel<<<hg2, 256>>>(h1a16, w2h, h2, 256, 128);
    alpha_h16_kernel<8><<<(N_NODES * 8 + 255) / 256, 256>>>(h2, at_s2, at_d2, pas2, pad2);
    stats_kernel<8><<<(N_NODES + 7) / 8, 256>>>(pas2, pad2);
    agg2_kernel<<<(N_NODES + 7) / 8, 256>>>(b2, out);
}

// round 13
// speedup vs baseline: 2.6398x; 1.2971x over previous
#include <cuda_runtime.h>
#include <cuda_fp16.h>
#include <math.h>
#include <mma.h>

using namespace nvcuda;

// Problem constants (fixed by the dataset)
#define N_NODES 50000
#define N_PAD   50048                        // 391 * 128
#define E_EDGES 800000
#define E_TOT   (E_EDGES + N_NODES)
#define SCAN_NB ((N_NODES + 1023) / 1024)   // 49

// ---------------- scratch (static __device__ allocations only) ----------------
__device__ __half g_x16[(size_t)N_PAD * 128];   // fp16 copy of x
__device__ __half g_h1a16[(size_t)N_PAD * 128]; // elu(gat1) fp16 (gemm2 input)
__device__ __half g_h16[(size_t)N_PAD * 256];   // fp16 h (per-layer stride)
__device__ __half g_w1h[128 * 128];
__device__ __half g_w2h[128 * 256];
__device__ float  g_ew [(size_t)E_TOT * 8];     // per-edge normalized weights
__device__ float  g_as1[N_NODES * 4];
__device__ float  g_ad1[N_NODES * 4];
__device__ float  g_as2[N_NODES * 8];
__device__ float  g_ad2[N_NODES * 8];
__device__ int    g_cnt[N_NODES];
__device__ int    g_tmp[N_NODES];
__device__ int    g_bsum[SCAN_NB];
__device__ int    g_boff[SCAN_NB];
__device__ int    g_rowptr[N_NODES + 1];
__device__ int    g_cursor[N_NODES];
__device__ int    g_col[E_TOT];
__device__ int    g_is64;

// ---------------- dtype detection for edge_index (int64 vs int32) -------------
__global__ void detect64_kernel(const unsigned int* __restrict__ w) {
    __shared__ int any;
    if (threadIdx.x == 0) any = 0;
    __syncthreads();
    for (int i = 1 + 2 * threadIdx.x; i < 2048; i += 2 * blockDim.x)
        if (w[i] != 0u) any = 1;   // benign race
    __syncthreads();
    if (threadIdx.x == 0) g_is64 = (any == 0) ? 1 : 0;
}

__global__ void zero_cnt_kernel() {
    int i = blockIdx.x * blockDim.x + threadIdx.x;
    if (i < N_NODES) g_cnt[i] = 0;
}

__global__ void count_kernel(const void* __restrict__ ei) {
    int e = blockIdx.x * blockDim.x + threadIdx.x;
    if (e >= E_TOT) return;
    int dst;
    if (e < E_EDGES) {
        if (g_is64) dst = (int)((const long long*)ei)[(size_t)E_EDGES + e];
        else        dst = ((const int*)ei)[E_EDGES + e];
    } else {
        dst = e - E_EDGES;   // self loop
    }
    atomicAdd(&g_cnt[dst], 1);
}

// ---------------- multi-block scan (3 tiny kernels) ---------------------------
__global__ void scan1_kernel() {
    int b = blockIdx.x, tid = threadIdx.x;
    int i = b * 1024 + tid;
    int lane = tid & 31, wid = tid >> 5;
    int v = (i < N_NODES) ? g_cnt[i] : 0;
    int x = v;
#pragma unroll
    for (int off = 1; off < 32; off <<= 1) {
        int t = __shfl_up_sync(0xffffffffu, x, off);
        if (lane >= off) x += t;
    }
    __shared__ int wsum[32];
    if (lane == 31) wsum[wid] = x;
    __syncthreads();
    if (wid == 0) {
        int y = wsum[lane];
#pragma unroll
        for (int off = 1; off < 32; off <<= 1) {
            int t = __shfl_up_sync(0xffffffffu, y, off);
            if (lane >= off) y += t;
        }
        wsum[lane] = y;
    }
    __syncthreads();
    int incl = x + (wid ? wsum[wid - 1] : 0);
    if (i < N_NODES) g_tmp[i] = incl;
    if (tid == 1023) g_bsum[b] = incl;
}

__global__ void scan2_kernel() {
    if (threadIdx.x == 0) {
        int run = 0;
#pragma unroll 1
        for (int j = 0; j < SCAN_NB; j++) { g_boff[j] = run; run += g_bsum[j]; }
        g_rowptr[0] = 0;
    }
}

__global__ void scan3_kernel() {
    int i = blockIdx.x * blockDim.x + threadIdx.x;
    if (i >= N_NODES) return;
    int incl = g_tmp[i] + g_boff[i >> 10];
    g_rowptr[i + 1] = incl;
    g_cursor[i]     = incl - g_cnt[i];
}

__global__ void scatter_kernel(const void* __restrict__ ei) {
    int e = blockIdx.x * blockDim.x + threadIdx.x;
    if (e >= E_TOT) return;
    int src, dst;
    if (e < E_EDGES) {
        if (g_is64) {
            const long long* p = (const long long*)ei;
            src = (int)p[e];
            dst = (int)p[(size_t)E_EDGES + e];
        } else {
            const int* p = (const int*)ei;
            src = p[e];
            dst = p[E_EDGES + e];
        }
    } else {
        src = dst = e - E_EDGES;
    }
    int pos = atomicAdd(&g_cursor[dst], 1);
    g_col[pos] = src;
}

// ---------------- fp32 -> fp16 conversions ------------------------------------
__global__ void convx_kernel(const float* __restrict__ x) {
    int i = blockIdx.x * blockDim.x + threadIdx.x;
    if (i >= N_NODES * 32) return;             // 128/4 float4s per row
    float4 v = ((const float4*)x)[i];
    ((__half2*)g_x16)[2 * i]     = __floats2half2_rn(v.x, v.y);
    ((__half2*)g_x16)[2 * i + 1] = __floats2half2_rn(v.z, v.w);
}

__global__ void convw_kernel(const float* __restrict__ W1,
                             const float* __restrict__ W2) {
    int i = blockIdx.x * blockDim.x + threadIdx.x;
    if (i < 4096) {                             // W1: 16384 floats
        float4 v = ((const float4*)W1)[i];
        ((__half2*)g_w1h)[2 * i]     = __floats2half2_rn(v.x, v.y);
        ((__half2*)g_w1h)[2 * i + 1] = __floats2half2_rn(v.z, v.w);
    } else if (i < 4096 + 8192) {               // W2: 32768 floats
        int j = i - 4096;
        float4 v = ((const float4*)W2)[j];
        ((__half2*)g_w2h)[2 * j]     = __floats2half2_rn(v.x, v.y);
        ((__half2*)g_w2h)[2 * j + 1] = __floats2half2_rn(v.z, v.w);
    }
}

// ------- fp16 tensor-core GEMM with fused alpha + fp16-store epilogue ---------
// C-tile (fp32 accum) -> smem -> per-(row,head) attention dots (as/ad) and
// fp16 feature store. A head = exactly 32 contiguous cols, so each (row,head)
// pair is fully owned by one block: no atomics. fp32 h never hits HBM.
#define HG_BM 128
#define HG_BN 64
#define HG_BK 32
#define HLDA 40
#define HLDB 72
#define CT_LD 72   // fp32 epilogue tile leading dim

#define SMEM_BYTES (HG_BM * CT_LD * 4)   // 36864 > Ah+Bh bytes (14848)

template <int H>
__global__ void hgemm_fused_kernel(const __half* __restrict__ A,
                                   const __half* __restrict__ Bw,
                                   __half* __restrict__ H16,
                                   float* __restrict__ as_out,
                                   float* __restrict__ ad_out,
                                   const float* __restrict__ att_s,
                                   const float* __restrict__ att_d,
                                   int K) {
    constexpr int N = H * 32;
    __shared__ __align__(16) char smraw[SMEM_BYTES];
    __half* Ah = (__half*)smraw;
    __half* Bh = (__half*)(smraw + HG_BM * HLDA * 2);
    float*  Ct = (float*)smraw;

    int tid = threadIdx.x;
    int wid = tid >> 5;
    int wm = wid & 3, wn = wid >> 2;
    size_t row0 = (size_t)blockIdx.y * HG_BM;
    int col0 = blockIdx.x * HG_BN;

    wmma::fragment<wmma::accumulator, 16, 16, 16, float> c[2][2];
#pragma unroll
    for (int i = 0; i < 2; i++)
#pragma unroll
        for (int j = 0; j < 2; j++) wmma::fill_fragment(c[i][j], 0.f);

    for (int k0 = 0; k0 < K; k0 += HG_BK) {
        // A tile: 128x32 halves = 512 uint4; 2 per thread
#pragma unroll
        for (int i = 0; i < 2; i++) {
            int f = tid + i * 256;
            int r = f >> 2, cc = (f & 3) * 8;
            *(uint4*)(Ah + r * HLDA + cc) =
                *(const uint4*)(A + (row0 + r) * K + k0 + cc);
        }
        // B tile: 32x64 halves = 256 uint4; 1 per thread
        {
            int r = tid >> 3, cc = (tid & 7) * 8;
            *(uint4*)(Bh + r * HLDB + cc) =
                *(const uint4*)(Bw + (size_t)(k0 + r) * N + col0 + cc);
        }
        __syncthreads();
#pragma unroll
        for (int kk = 0; kk < HG_BK; kk += 16) {
            wmma::fragment<wmma::matrix_a, 16, 16, 16, __half, wmma::row_major> a[2];
            wmma::fragment<wmma::matrix_b, 16, 16, 16, __half, wmma::row_major> b[2];
#pragma unroll
            for (int mi = 0; mi < 2; mi++)
                wmma::load_matrix_sync(a[mi], Ah + (wm * 32 + mi * 16) * HLDA + kk, HLDA);
#pragma unroll
            for (int ni = 0; ni < 2; ni++)
                wmma::load_matrix_sync(b[ni], Bh + kk * HLDB + wn * 32 + ni * 16, HLDB);
#pragma unroll
            for (int mi = 0; mi < 2; mi++)
#pragma unroll
                for (int ni = 0; ni < 2; ni++)
                    wmma::mma_sync(c[mi][ni], a[mi], b[ni], c[mi][ni]);
        }
        __syncthreads();
    }

    // epilogue: spill fp32 tile to smem (operand buffers are dead now)
#pragma unroll
    for (int mi = 0; mi < 2; mi++)
#pragma unroll
        for (int ni = 0; ni < 2; ni++)
            wmma::store_matrix_sync(
                Ct + (wm * 32 + mi * 16) * CT_LD + wn * 32 + ni * 16,
                c[mi][ni], CT_LD, wmma::mem_row_major);
    __syncthreads();

    // each thread owns one (row, 32-col head slice): dots + fp16 store
    int row = tid >> 1;
    int seg = tid & 1;
    size_t node = row0 + row;
    int head = (col0 >> 5) + seg;
    const float* Crow = Ct + row * CT_LD + seg * 32;
    const float* a1 = att_s + head * 32;
    const float* a2 = att_d + head * 32;

    float s1 = 0.f, s2 = 0.f;
    __half hv[32];
#pragma unroll
    for (int j = 0; j < 32; j += 4) {
        float4 v  = *(const float4*)(Crow + j);
        float4 w1 = *(const float4*)(a1 + j);
        float4 w2 = *(const float4*)(a2 + j);
        s1 += v.x * w1.x + v.y * w1.y + v.z * w1.z + v.w * w1.w;
        s2 += v.x * w2.x + v.y * w2.y + v.z * w2.z + v.w * w2.w;
        *(__half2*)(hv + j)     = __floats2half2_rn(v.x, v.y);
        *(__half2*)(hv + j + 2) = __floats2half2_rn(v.z, v.w);
    }
    __half* hp = H16 + node * N + col0 + seg * 32;
#pragma unroll
    for (int j = 0; j < 4; j++)
        ((uint4*)hp)[j] = ((uint4*)hv)[j];
    if (node < N_NODES) {
        as_out[node * H + head] = s1;
        ad_out[node * H + head] = s2;
    }
}

// ------- stats + per-edge weight precompute: one warp per destination node ----
template <int H>
__global__ void stats_kernel(const float* __restrict__ asrc,
                             const float* __restrict__ adst) {
    int w    = (blockIdx.x * blockDim.x + threadIdx.x) >> 5;
    int lane = threadIdx.x & 31;
    if (w >= N_NODES) return;
    int beg = g_rowptr[w], end = g_rowptr[w + 1];

    float ad[H];
#pragma unroll
    for (int h = 0; h < H; h++) ad[h] = adst[(size_t)w * H + h];

    float m[H], s[H];
#pragma unroll
    for (int h = 0; h < H; h++) { m[h] = -1e30f; s[h] = 0.f; }
    for (int e = beg + lane; e < end; e += 32) {
        int src = g_col[e];
        const float4* ap4 = (const float4*)(asrc + (size_t)src * H);
        float av[H];
#pragma unroll
        for (int q = 0; q < H / 4; q++) {
            float4 t = ap4[q];
            av[4 * q] = t.x; av[4 * q + 1] = t.y; av[4 * q + 2] = t.z; av[4 * q + 3] = t.w;
        }
#pragma unroll
        for (int h = 0; h < H; h++) {
            float x = av[h] + ad[h];
            x = x > 0.f ? x : 0.2f * x;
            if (x > m[h]) {
                s[h] = s[h] * __expf(m[h] - x) + 1.f;
                m[h] = x;
            } else {
                s[h] += __expf(x - m[h]);
            }
        }
    }
#pragma unroll
    for (int h = 0; h < H; h++) {
        float mw = m[h];
#pragma unroll
        for (int off = 16; off; off >>= 1)
            mw = fmaxf(mw, __shfl_xor_sync(0xffffffffu, mw, off));
        float sw = s[h] * __expf(m[h] - mw);
#pragma unroll
        for (int off = 16; off; off >>= 1)
            sw += __shfl_xor_sync(0xffffffffu, sw, off);
        m[h] = mw;
        s[h] = 1.f / sw;     // inv_s
    }

    for (int e = beg + lane; e < end; e += 32) {
        int src = g_col[e];
        const float4* ap4 = (const float4*)(asrc + (size_t)src * H);
        float av[H], wv[H];
#pragma unroll
        for (int q = 0; q < H / 4; q++) {
            float4 t = ap4[q];
            av[4 * q] = t.x; av[4 * q + 1] = t.y; av[4 * q + 2] = t.z; av[4 * q + 3] = t.w;
        }
#pragma unroll
        for (int h = 0; h < H; h++) {
            float x = av[h] + ad[h];
            x = x > 0.f ? x : 0.2f * x;
            wv[h] = __expf(x - m[h]) * s[h];
        }
        float4* wp = (float4*)(g_ew + (size_t)e * H);
#pragma unroll
        for (int q = 0; q < H / 4; q++)
            wp[q] = make_float4(wv[4 * q], wv[4 * q + 1], wv[4 * q + 2], wv[4 * q + 3]);
    }
}

// ------- aggregation: one warp per node, fp16 gathers, fp32 accum -------------
// Layer 1 (H=4, concat+ELU): writes fp16 h1a directly (gemm2 input).
__global__ void agg1_kernel(const float* __restrict__ bias) {
    int w    = (blockIdx.x * blockDim.x + threadIdx.x) >> 5;
    int lane = threadIdx.x & 31;
    if (w >= N_NODES) return;
    int beg = g_rowptr[w], end = g_rowptr[w + 1];
    int hsel = lane >> 3;

    float acc[4] = {0.f, 0.f, 0.f, 0.f};
    for (int e = beg; e < end; e++) {
        int src = g_col[e];
        float wt = g_ew[(size_t)e * 4 + hsel];
        uint2 hv = *((const uint2*)(g_h16 + (size_t)src * 128) + lane);
        float2 f0 = __half22float2(*(__half2*)&hv.x);
        float2 f1 = __half22float2(*(__half2*)&hv.y);
        acc[0] += f0.x * wt;
        acc[1] += f0.y * wt;
        acc[2] += f1.x * wt;
        acc[3] += f1.y * wt;
    }
    float4 bv = *((const float4*)bias + lane);
    float4 o;
    o.x = acc[0] + bv.x; o.y = acc[1] + bv.y; o.z = acc[2] + bv.z; o.w = acc[3] + bv.w;
    o.x = o.x > 0.f ? o.x : expm1f(o.x);
    o.y = o.y > 0.f ? o.y : expm1f(o.y);
    o.z = o.z > 0.f ? o.z : expm1f(o.z);
    o.w = o.w > 0.f ? o.w : expm1f(o.w);
    uint2 o16;
    *(__half2*)&o16.x = __floats2half2_rn(o.x, o.y);
    *(__half2*)&o16.y = __floats2half2_rn(o.z, o.w);
    ((uint2*)(g_h1a16 + (size_t)w * 128))[lane] = o16;
}

// Layer 2 (H=8, mean over heads).
__global__ void agg2_kernel(const float* __restrict__ bias,
                            float* __restrict__ out) {
    int w    = (blockIdx.x * blockDim.x + threadIdx.x) >> 5;
    int lane = threadIdx.x & 31;
    if (w >= N_NODES) return;
    int beg = g_rowptr[w], end = g_rowptr[w + 1];
    int hsel = lane >> 2;

    float acc[8];
#pragma unroll
    for (int j = 0; j < 8; j++) acc[j] = 0.f;

    for (int e = beg; e < end; e++) {
        int src = g_col[e];
        float wt = g_ew[(size_t)e * 8 + hsel];
        uint4 hv = *((const uint4*)(g_h16 + (size_t)src * 256) + lane);
        float2 f0 = __half22float2(*(__half2*)&hv.x);
        float2 f1 = __half22float2(*(__half2*)&hv.y);
        float2 f2 = __half22float2(*(__half2*)&hv.z);
        float2 f3 = __half22float2(*(__half2*)&hv.w);
        acc[0] += f0.x * wt; acc[1] += f0.y * wt;
        acc[2] += f1.x * wt; acc[3] += f1.y * wt;
        acc[4] += f2.x * wt; acc[5] += f2.y * wt;
        acc[6] += f3.x * wt; acc[7] += f3.y * wt;
    }
#pragma unroll
    for (int off = 4; off < 32; off <<= 1)
#pragma unroll
        for (int j = 0; j < 8; j++)
            acc[j] += __shfl_xor_sync(0xffffffffu, acc[j], off);

    if (lane < 4) {
        int c0 = lane * 8;
        float4 b0 = *(const float4*)(bias + c0);
        float4 b1 = *(const float4*)(bias + c0 + 4);
        float4 o0, o1;
        o0.x = acc[0] * 0.125f + b0.x; o0.y = acc[1] * 0.125f + b0.y;
        o0.z = acc[2] * 0.125f + b0.z; o0.w = acc[3] * 0.125f + b0.w;
        o1.x = acc[4] * 0.125f + b1.x; o1.y = acc[5] * 0.125f + b1.y;
        o1.z = acc[6] * 0.125f + b1.z; o1.w = acc[7] * 0.125f + b1.w;
        *(float4*)(out + (size_t)w * 32 + c0)     = o0;
        *(float4*)(out + (size_t)w * 32 + c0 + 4) = o1;
    }
}

// ---------------- launch ------------------------------------------------------
extern "C" void kernel_launch(void* const* d_in, const int* in_sizes, int n_in,
                              void* d_out, int out_size) {
    const float* x   = (const float*)d_in[0];
    const void*  ei  = d_in[1];
    const float* W1  = (const float*)d_in[2];
    const float* at_s1 = (const float*)d_in[3];
    const float* at_d1 = (const float*)d_in[4];
    const float* b1  = (const float*)d_in[5];
    const float* W2  = (const float*)d_in[6];
    const float* at_s2 = (const float*)d_in[7];
    const float* at_d2 = (const float*)d_in[8];
    const float* b2  = (const float*)d_in[9];
    float* out = (float*)d_out;

    float *pas1, *pad1, *pas2, *pad2;
    __half *x16, *w1h, *w2h, *h1a16, *h16;
    cudaGetSymbolAddress((void**)&x16, g_x16);
    cudaGetSymbolAddress((void**)&w1h, g_w1h);
    cudaGetSymbolAddress((void**)&w2h, g_w2h);
    cudaGetSymbolAddress((void**)&h1a16, g_h1a16);
    cudaGetSymbolAddress((void**)&h16, g_h16);
    cudaGetSymbolAddress((void**)&pas1, g_as1);
    cudaGetSymbolAddress((void**)&pad1, g_ad1);
    cudaGetSymbolAddress((void**)&pas2, g_as2);
    cudaGetSymbolAddress((void**)&pad2, g_ad2);

    // CSR build + fp16 conversions (conversions independent of CSR)
    detect64_kernel<<<1, 256>>>((const unsigned int*)ei);
    zero_cnt_kernel<<<(N_NODES + 255) / 256, 256>>>();
    count_kernel<<<(E_TOT + 255) / 256, 256>>>(ei);
    convx_kernel<<<(N_NODES * 32 + 255) / 256, 256>>>(x);
    convw_kernel<<<(12288 + 255) / 256, 256>>>(W1, W2);
    scan1_kernel<<<SCAN_NB, 1024>>>();
    scan2_kernel<<<1, 32>>>();
    scan3_kernel<<<(N_NODES + 255) / 256, 256>>>();
    scatter_kernel<<<(E_TOT + 255) / 256, 256>>>(ei);

    dim3 hg1(128 / HG_BN, N_PAD / HG_BM);   // (2, 391)
    dim3 hg2(256 / HG_BN, N_PAD / HG_BM);   // (4, 391)

    // layer 1
    hgemm_fused_kernel<4><<<hg1, 256>>>(x16, w1h, h16, pas1, pad1, at_s1, at_d1, 128);
    stats_kernel<4><<<(N_NODES + 7) / 8, 256>>>(pas1, pad1);
    agg1_kernel<<<(N_NODES + 7) / 8, 256>>>(b1);

    // layer 2
    hgemm_fused_kernel<8><<<hg2, 256>>>(h1a16, w2h, h16, pas2, pad2, at_s2, at_d2, 128);
    stats_kernel<8><<<(N_NODES + 7) / 8, 256>>>(pas2, pad2);
    agg2_kernel<<<(N_NODES + 7) / 8, 256>>>(b2, out);
}